// round 6
// baseline (speedup 1.0000x reference)
#include <cuda_runtime.h>
#include <cuda_bf16.h>
#include <math.h>
#include <cstdint>

// Problem constants: B=2, T=2048, DIM=2048, H=16, KV=4, D=128, G=4
#define BT 4096
#define CDIM 2048
#define KVDIM 512

// Scratch (device globals; no allocation allowed)
__device__ float g_q[(size_t)BT * CDIM];
__device__ float g_k[(size_t)BT * KVDIM];
__device__ float g_v[(size_t)BT * KVDIM];
__device__ float g_att[(size_t)BT * CDIM];

// ---------------------------------------------------------------------------
// mma.sync m16n8k16 bf16 (sm_80-class; compiles at compute_100)
// ---------------------------------------------------------------------------
__device__ __forceinline__ void mma16816(
    float c[4], uint32_t a0, uint32_t a1, uint32_t a2, uint32_t a3,
    uint32_t b0, uint32_t b1)
{
    asm volatile(
        "mma.sync.aligned.m16n8k16.row.col.f32.bf16.bf16.f32 "
        "{%0,%1,%2,%3}, {%4,%5,%6,%7}, {%8,%9}, {%0,%1,%2,%3};"
        : "+f"(c[0]), "+f"(c[1]), "+f"(c[2]), "+f"(c[3])
        : "r"(a0), "r"(a1), "r"(a2), "r"(a3), "r"(b0), "r"(b1));
}

// split float4 into hi-bf16 pair-words and lo-bf16 pair-words
__device__ __forceinline__ void split4(float4 v, uint2& hi, uint2& lo) {
    __nv_bfloat16 hx = __float2bfloat16(v.x); float rx = v.x - __bfloat162float(hx);
    __nv_bfloat16 hy = __float2bfloat16(v.y); float ry = v.y - __bfloat162float(hy);
    __nv_bfloat16 hz = __float2bfloat16(v.z); float rz = v.z - __bfloat162float(hz);
    __nv_bfloat16 hw = __float2bfloat16(v.w); float rw = v.w - __bfloat162float(hw);
    hi.x = (uint32_t)__bfloat16_as_ushort(hx) | ((uint32_t)__bfloat16_as_ushort(hy) << 16);
    hi.y = (uint32_t)__bfloat16_as_ushort(hz) | ((uint32_t)__bfloat16_as_ushort(hw) << 16);
    lo.x = (uint32_t)__bfloat16_as_ushort(__float2bfloat16(rx))
         | ((uint32_t)__bfloat16_as_ushort(__float2bfloat16(ry)) << 16);
    lo.y = (uint32_t)__bfloat16_as_ushort(__float2bfloat16(rz))
         | ((uint32_t)__bfloat16_as_ushort(__float2bfloat16(rw)) << 16);
}

// swizzled word index inside a [128 rows x 32 words] tile (128B rows)
__device__ __forceinline__ uint32_t swz(uint32_t r, uint32_t w) {
    return r * 32u + (w ^ ((r & 7u) << 2));
}

// ===========================================================================
// mma.sync bf16 split-3-pass NT GEMM: C[M,N] = A[M,K]*B[N,K]^T + bias[N]
// CTA 128x128, 8 warps (2x4), warp tile 64x32.
// K chunk = 32 floats. Row layout: words 0-15 = hi bf16, words 16-31 = lo.
// Per chunk: 3 passes (Ah*Bh, Ah*Bl, Al*Bh) x 2 k16-steps.
// Double-buffered smem: 2 * (16KB A + 16KB B).
// ===========================================================================
#define GEMM_SMEM (4 * 16384)

__global__ __launch_bounds__(256) void gemm_mma(
    const float* __restrict__ A, const float* __restrict__ B,
    const float* __restrict__ bias, float* __restrict__ C,
    int M, int N, int K)
{
    extern __shared__ uint32_t smw[];   // [2][ A:4096 words | B:4096 words ]

    const int tid = threadIdx.x;
    const int wid = tid >> 5;
    const int lane = tid & 31;
    const int bm = blockIdx.y * 128;
    const int bn = blockIdx.x * 128;

    const int wm = wid >> 2;            // 0..1  (M)
    const int wn = wid & 3;             // 0..3  (N)

    // global load mapping: thread -> rows r0+32i, float4-col c4
    const int r0 = tid >> 3;            // 0..31
    const int c4 = tid & 7;             // 0..7
    const float* Ag = A + (size_t)(bm + r0) * K + c4 * 4;
    const float* Bg = B + (size_t)(bn + r0) * K + c4 * 4;
    const size_t strA = (size_t)32 * K;

    const int nchunk = K >> 5;

    float acc[4][4][4];
#pragma unroll
    for (int mt = 0; mt < 4; mt++)
#pragma unroll
        for (int nt = 0; nt < 4; nt++)
#pragma unroll
            for (int e = 0; e < 4; e++) acc[mt][nt][e] = 0.0f;

    float4 ra[4], rb[4];
#pragma unroll
    for (int i = 0; i < 4; i++) {
        ra[i] = *(const float4*)(Ag + i * strA);
        rb[i] = *(const float4*)(Bg + i * strA);
    }
    // store chunk 0 into stage 0
    {
        uint32_t* As = smw;
        uint32_t* Bs = smw + 4096;
#pragma unroll
        for (int i = 0; i < 4; i++) {
            uint32_t r = r0 + i * 32;
            uint2 hi, lo;
            split4(ra[i], hi, lo);
            *(uint2*)(As + swz(r, c4 * 2))       = hi;
            *(uint2*)(As + swz(r, 16 + c4 * 2))  = lo;
            split4(rb[i], hi, lo);
            *(uint2*)(Bs + swz(r, c4 * 2))       = hi;
            *(uint2*)(Bs + swz(r, 16 + c4 * 2))  = lo;
        }
    }

    const int lr = lane >> 2;           // 0..7
    const int lw = lane & 3;            // 0..3

    for (int c = 0; c < nchunk; ++c) {
        // prefetch next chunk
        if (c + 1 < nchunk) {
#pragma unroll
            for (int i = 0; i < 4; i++) {
                ra[i] = *(const float4*)(Ag + (c + 1) * 32 + i * strA);
                rb[i] = *(const float4*)(Bg + (c + 1) * 32 + i * strA);
            }
        }
        __syncthreads();

        uint32_t* As = smw + (c & 1) * 8192;
        uint32_t* Bs = As + 4096;

        // 3 passes: (Ah,Bh), (Ah,Bl), (Al,Bh); each pass 2 k16-steps
#pragma unroll
        for (int pass = 0; pass < 3; pass++) {
            const uint32_t aoff = (pass == 2) ? 16u : 0u;
            const uint32_t boff = (pass == 1) ? 16u : 0u;
#pragma unroll
            for (int s = 0; s < 2; s++) {
                const uint32_t kwa = aoff + s * 8 + lw;
                const uint32_t kwb = boff + s * 8 + lw;
                uint32_t bfr[4][2];
#pragma unroll
                for (int nt = 0; nt < 4; nt++) {
                    uint32_t n = wn * 32 + nt * 8 + lr;
                    bfr[nt][0] = Bs[swz(n, kwb)];
                    bfr[nt][1] = Bs[swz(n, kwb + 4)];
                }
#pragma unroll
                for (int mt = 0; mt < 4; mt++) {
                    uint32_t rrow = wm * 64 + mt * 16 + lr;
                    uint32_t a0 = As[swz(rrow, kwa)];
                    uint32_t a1 = As[swz(rrow + 8, kwa)];
                    uint32_t a2 = As[swz(rrow, kwa + 4)];
                    uint32_t a3 = As[swz(rrow + 8, kwa + 4)];
#pragma unroll
                    for (int nt = 0; nt < 4; nt++)
                        mma16816(acc[mt][nt], a0, a1, a2, a3,
                                 bfr[nt][0], bfr[nt][1]);
                }
            }
        }

        // store next chunk into other stage
        if (c + 1 < nchunk) {
            uint32_t* An = smw + ((c + 1) & 1) * 8192;
            uint32_t* Bn = An + 4096;
#pragma unroll
            for (int i = 0; i < 4; i++) {
                uint32_t r = r0 + i * 32;
                uint2 hi, lo;
                split4(ra[i], hi, lo);
                *(uint2*)(An + swz(r, c4 * 2))       = hi;
                *(uint2*)(An + swz(r, 16 + c4 * 2))  = lo;
                split4(rb[i], hi, lo);
                *(uint2*)(Bn + swz(r, c4 * 2))       = hi;
                *(uint2*)(Bn + swz(r, 16 + c4 * 2))  = lo;
            }
        }
    }

    // epilogue: acc -> gmem (+bias). c0,c1 at (row, col..col+1); c2,c3 row+8.
#pragma unroll
    for (int mt = 0; mt < 4; mt++) {
        int row = bm + wm * 64 + mt * 16 + lr;
#pragma unroll
        for (int nt = 0; nt < 4; nt++) {
            int col = bn + wn * 32 + nt * 8 + lw * 2;
            float b0 = bias[col], b1 = bias[col + 1];
            float2 v0 = make_float2(acc[mt][nt][0] + b0, acc[mt][nt][1] + b1);
            float2 v1 = make_float2(acc[mt][nt][2] + b0, acc[mt][nt][3] + b1);
            *(float2*)(C + (size_t)row * N + col) = v0;
            *(float2*)(C + (size_t)(row + 8) * N + col) = v1;
        }
    }
}

// ---------------------------------------------------------------------------
// RoPE (head-indexed angles per the reference's slicing quirk)
// ---------------------------------------------------------------------------
__global__ void rope_kernel(float* __restrict__ data, int heads)
{
    int idx = blockIdx.x * blockDim.x + threadIdx.x;
    int total = BT * heads * 64;
    if (idx >= total) return;
    int d = idx & 63;
    int h = (idx >> 6) % heads;
    int row = idx / (heads * 64);

    float invf = powf(10000.0f, -(float)d / 64.0f);
    float ang = (float)h * invf;
    float c = cosf(ang);
    float s = sinf(ang);

    float* p = data + (size_t)row * heads * 128 + h * 128;
    float x1 = p[d];
    float x2 = p[d + 64];
    p[d]      = x1 * c - x2 * s;
    p[d + 64] = x2 * c + x1 * s;
}

// ---------------------------------------------------------------------------
// Flash-style attention (additive mask per reference), fp32 SIMT.
// Identical to the Round-1 passing version (expf -> __expf).
// ---------------------------------------------------------------------------
#define QK_LD 68
#define PS_LD 68

__global__ __launch_bounds__(256) void attn_kernel(
    const float* __restrict__ q, const float* __restrict__ k,
    const float* __restrict__ v, float* __restrict__ o)
{
    extern __shared__ float smf[];
    float* Qs = smf;
    float* KV = smf + 128 * QK_LD;
    float* Ps = smf + 2 * 128 * QK_LD;

    const int tid = threadIdx.x;
    const int tx = tid & 15;
    const int ty = tid >> 4;
    const int t0 = blockIdx.x * 64;
    const int bh = blockIdx.y;
    const int b = bh >> 4;
    const int kv = (bh >> 2) & 3;
    const int h = bh & 15;

    const float scale = 0.08838834764831845f;

    {
        const size_t qbase = ((size_t)(b * 2048 + t0)) * CDIM + h * 128;
#pragma unroll
        for (int it = 0; it < 8; it++) {
            int f = tid + it * 256;
            int r = f >> 5;
            int c4v = f & 31;
            float4 val = *(const float4*)(q + qbase + (size_t)r * CDIM + c4v * 4);
            int d = c4v * 4;
            Qs[(d + 0) * QK_LD + r] = val.x * scale;
            Qs[(d + 1) * QK_LD + r] = val.y * scale;
            Qs[(d + 2) * QK_LD + r] = val.z * scale;
            Qs[(d + 3) * QK_LD + r] = val.w * scale;
        }
    }

    float m_i[4], l_i[4], accO[4][8];
#pragma unroll
    for (int i = 0; i < 4; i++) {
        m_i[i] = -INFINITY;
        l_i[i] = 0.0f;
#pragma unroll
        for (int j = 0; j < 8; j++) accO[i][j] = 0.0f;
    }

    for (int s0 = 0; s0 < 2048; s0 += 64) {
        __syncthreads();
        {
            const size_t kbase = ((size_t)(b * 2048 + s0)) * KVDIM + kv * 128;
#pragma unroll
            for (int it = 0; it < 8; it++) {
                int f = tid + it * 256;
                int r = f >> 5;
                int c4v = f & 31;
                float4 val = *(const float4*)(k + kbase + (size_t)r * KVDIM + c4v * 4);
                int d = c4v * 4;
                KV[(d + 0) * QK_LD + r] = val.x;
                KV[(d + 1) * QK_LD + r] = val.y;
                KV[(d + 2) * QK_LD + r] = val.z;
                KV[(d + 3) * QK_LD + r] = val.w;
            }
        }
        __syncthreads();

        float accS[4][4];
#pragma unroll
        for (int i = 0; i < 4; i++)
#pragma unroll
            for (int j = 0; j < 4; j++) accS[i][j] = 0.0f;

#pragma unroll 4
        for (int d = 0; d < 128; d++) {
            float qv[4], kw[4];
            *(float4*)qv = *(const float4*)&Qs[d * QK_LD + ty * 4];
            *(float4*)kw = *(const float4*)&KV[d * QK_LD + tx * 4];
#pragma unroll
            for (int i = 0; i < 4; i++)
#pragma unroll
                for (int j = 0; j < 4; j++)
                    accS[i][j] += qv[i] * kw[j];
        }

        __syncthreads();

        {
            const size_t vbase = ((size_t)(b * 2048 + s0)) * KVDIM + kv * 128;
#pragma unroll
            for (int it = 0; it < 8; it++) {
                int f = tid + it * 256;
                int r = f >> 5;
                int c4v = f & 31;
                *(float4*)&KV[r * 128 + c4v * 4] =
                    *(const float4*)(v + vbase + (size_t)r * KVDIM + c4v * 4);
            }
        }

#pragma unroll
        for (int i = 0; i < 4; i++) {
            int t = t0 + ty * 4 + i;
#pragma unroll
            for (int j = 0; j < 4; j++) {
                int s = s0 + tx * 4 + j;
                if (s <= t) accS[i][j] += 1.0f;
            }
            float rmax = fmaxf(fmaxf(accS[i][0], accS[i][1]),
                               fmaxf(accS[i][2], accS[i][3]));
#pragma unroll
            for (int off = 8; off > 0; off >>= 1)
                rmax = fmaxf(rmax, __shfl_xor_sync(0xffffffffu, rmax, off));
            float mnew = fmaxf(m_i[i], rmax);
            float fac = __expf(m_i[i] - mnew);
            m_i[i] = mnew;
            float rsum = 0.0f;
#pragma unroll
            for (int j = 0; j < 4; j++) {
                float e = __expf(accS[i][j] - mnew);
                Ps[(ty * 4 + i) * PS_LD + tx * 4 + j] = e;
                rsum += e;
            }
#pragma unroll
            for (int off = 8; off > 0; off >>= 1)
                rsum += __shfl_xor_sync(0xffffffffu, rsum, off);
            l_i[i] = l_i[i] * fac + rsum;
#pragma unroll
            for (int j = 0; j < 8; j++) accO[i][j] *= fac;
        }
        __syncthreads();

#pragma unroll 2
        for (int s = 0; s < 64; s++) {
            float p0 = Ps[(ty * 4 + 0) * PS_LD + s];
            float p1 = Ps[(ty * 4 + 1) * PS_LD + s];
            float p2 = Ps[(ty * 4 + 2) * PS_LD + s];
            float p3 = Ps[(ty * 4 + 3) * PS_LD + s];
            float va[8];
            *(float4*)(va)     = *(const float4*)&KV[s * 128 + tx * 4];
            *(float4*)(va + 4) = *(const float4*)&KV[s * 128 + 64 + tx * 4];
#pragma unroll
            for (int j = 0; j < 8; j++) {
                accO[0][j] += p0 * va[j];
                accO[1][j] += p1 * va[j];
                accO[2][j] += p2 * va[j];
                accO[3][j] += p3 * va[j];
            }
        }
    }

    const size_t obase = ((size_t)(b * 2048 + t0)) * CDIM + h * 128;
#pragma unroll
    for (int i = 0; i < 4; i++) {
        float inv = 1.0f / l_i[i];
        int tl = ty * 4 + i;
        float4 o0, o1;
        o0.x = accO[i][0] * inv; o0.y = accO[i][1] * inv;
        o0.z = accO[i][2] * inv; o0.w = accO[i][3] * inv;
        o1.x = accO[i][4] * inv; o1.y = accO[i][5] * inv;
        o1.z = accO[i][6] * inv; o1.w = accO[i][7] * inv;
        *(float4*)(o + obase + (size_t)tl * CDIM + tx * 4) = o0;
        *(float4*)(o + obase + (size_t)tl * CDIM + 64 + tx * 4) = o1;
    }
}

// ---------------------------------------------------------------------------
extern "C" void kernel_launch(void* const* d_in, const int* in_sizes, int n_in,
                              void* d_out, int out_size)
{
    const float* x  = (const float*)d_in[0];
    const float* wq = (const float*)d_in[1];
    const float* bq = (const float*)d_in[2];
    const float* wk = (const float*)d_in[3];
    const float* bk = (const float*)d_in[4];
    const float* wv = (const float*)d_in[5];
    const float* bv = (const float*)d_in[6];
    const float* wo = (const float*)d_in[7];
    const float* bo = (const float*)d_in[8];
    float* out = (float*)d_out;

    float *qp, *kp, *vp, *ap;
    cudaGetSymbolAddress((void**)&qp, g_q);
    cudaGetSymbolAddress((void**)&kp, g_k);
    cudaGetSymbolAddress((void**)&vp, g_v);
    cudaGetSymbolAddress((void**)&ap, g_att);

    cudaFuncSetAttribute(gemm_mma,
                         cudaFuncAttributeMaxDynamicSharedMemorySize, GEMM_SMEM);

    // QKV projections (mma.sync bf16 3-pass split)
    gemm_mma<<<dim3(16, 32), 256, GEMM_SMEM>>>(x, wq, bq, qp, BT, CDIM, CDIM);
    gemm_mma<<<dim3(4, 32), 256, GEMM_SMEM>>>(x, wk, bk, kp, BT, KVDIM, CDIM);
    gemm_mma<<<dim3(4, 32), 256, GEMM_SMEM>>>(x, wv, bv, vp, BT, KVDIM, CDIM);

    // RoPE
    rope_kernel<<<(BT * 16 * 64 + 255) / 256, 256>>>(qp, 16);
    rope_kernel<<<(BT * 4 * 64 + 255) / 256, 256>>>(kp, 4);

    // Attention
    const int attn_smem = (2 * 128 * QK_LD + 64 * PS_LD) * (int)sizeof(float);
    cudaFuncSetAttribute(attn_kernel,
                         cudaFuncAttributeMaxDynamicSharedMemorySize, attn_smem);
    attn_kernel<<<dim3(32, 32), 256, attn_smem>>>(qp, kp, vp, ap);

    // Output projection
    gemm_mma<<<dim3(16, 32), 256, GEMM_SMEM>>>(ap, wo, bo, out, BT, CDIM, CDIM);
}

// round 8
// speedup vs baseline: 1.6013x; 1.6013x over previous
#include <cuda_runtime.h>
#include <cuda_bf16.h>
#include <math.h>
#include <cstdint>

#define BT 4096
#define CDIM 2048
#define KVDIM 512

__device__ float g_q[(size_t)BT * CDIM];
__device__ float g_k[(size_t)BT * KVDIM];
__device__ float g_v[(size_t)BT * KVDIM];
__device__ float g_att[(size_t)BT * CDIM];

__device__ __forceinline__ void mma16816(
    float c[4], uint32_t a0, uint32_t a1, uint32_t a2, uint32_t a3,
    uint32_t b0, uint32_t b1)
{
    asm volatile(
        "mma.sync.aligned.m16n8k16.row.col.f32.bf16.bf16.f32 "
        "{%0,%1,%2,%3}, {%4,%5,%6,%7}, {%8,%9}, {%0,%1,%2,%3};"
        : "+f"(c[0]), "+f"(c[1]), "+f"(c[2]), "+f"(c[3])
        : "r"(a0), "r"(a1), "r"(a2), "r"(a3), "r"(b0), "r"(b1));
}

__device__ __forceinline__ void split4(float4 v, uint2& hi, uint2& lo) {
    __nv_bfloat16 hx = __float2bfloat16(v.x); float rx = v.x - __bfloat162float(hx);
    __nv_bfloat16 hy = __float2bfloat16(v.y); float ry = v.y - __bfloat162float(hy);
    __nv_bfloat16 hz = __float2bfloat16(v.z); float rz = v.z - __bfloat162float(hz);
    __nv_bfloat16 hw = __float2bfloat16(v.w); float rw = v.w - __bfloat162float(hw);
    hi.x = (uint32_t)__bfloat16_as_ushort(hx) | ((uint32_t)__bfloat16_as_ushort(hy) << 16);
    hi.y = (uint32_t)__bfloat16_as_ushort(hz) | ((uint32_t)__bfloat16_as_ushort(hw) << 16);
    lo.x = (uint32_t)__bfloat16_as_ushort(__float2bfloat16(rx))
         | ((uint32_t)__bfloat16_as_ushort(__float2bfloat16(ry)) << 16);
    lo.y = (uint32_t)__bfloat16_as_ushort(__float2bfloat16(rz))
         | ((uint32_t)__bfloat16_as_ushort(__float2bfloat16(rw)) << 16);
}

__device__ __forceinline__ void pksplit(float a, float b, uint32_t& hi, uint32_t& lo) {
    __nv_bfloat16 ha = __float2bfloat16(a), hb = __float2bfloat16(b);
    float ra = a - __bfloat162float(ha), rb = b - __bfloat162float(hb);
    hi = (uint32_t)__bfloat16_as_ushort(ha) | ((uint32_t)__bfloat16_as_ushort(hb) << 16);
    lo = (uint32_t)__bfloat16_as_ushort(__float2bfloat16(ra))
       | ((uint32_t)__bfloat16_as_ushort(__float2bfloat16(rb)) << 16);
}

__device__ __forceinline__ uint32_t swz(uint32_t r, uint32_t w) {
    return r * 32u + (w ^ ((r & 7u) << 2));
}

// exp for x<=0 on FMA pipe
__device__ __forceinline__ float fexp(float x) {
    float t = fmaxf(x * 1.4426950408889634f, -126.0f);
    float r = rintf(t);
    float u = (t - r) * 0.6931471805599453f;
    float p = 0.008333333333f;
    p = fmaf(p, u, 0.041666666667f);
    p = fmaf(p, u, 0.166666666667f);
    p = fmaf(p, u, 0.5f);
    p = fmaf(p, u, 1.0f);
    p = fmaf(p, u, 1.0f);
    return p * __int_as_float(((int)r + 127) << 23);
}

// ===== GEMM (unchanged from passing Round 5) =====
#define GEMM_SMEM (4 * 16384)

__global__ __launch_bounds__(256) void gemm_mma(
    const float* __restrict__ A, const float* __restrict__ B,
    const float* __restrict__ bias, float* __restrict__ C,
    int M, int N, int K)
{
    extern __shared__ uint32_t smw[];
    const int tid = threadIdx.x;
    const int wid = tid >> 5, lane = tid & 31;
    const int bm = blockIdx.y * 128, bn = blockIdx.x * 128;
    const int wm = wid >> 2, wn = wid & 3;
    const int r0 = tid >> 3, c4 = tid & 7;
    const float* Ag = A + (size_t)(bm + r0) * K + c4 * 4;
    const float* Bg = B + (size_t)(bn + r0) * K + c4 * 4;
    const size_t strA = (size_t)32 * K;
    const int nchunk = K >> 5;

    float acc[4][4][4];
#pragma unroll
    for (int mt = 0; mt < 4; mt++)
#pragma unroll
        for (int nt = 0; nt < 4; nt++)
#pragma unroll
            for (int e = 0; e < 4; e++) acc[mt][nt][e] = 0.0f;

    float4 ra[4], rb[4];
#pragma unroll
    for (int i = 0; i < 4; i++) {
        ra[i] = *(const float4*)(Ag + i * strA);
        rb[i] = *(const float4*)(Bg + i * strA);
    }
    {
        uint32_t* As = smw; uint32_t* Bs = smw + 4096;
#pragma unroll
        for (int i = 0; i < 4; i++) {
            uint32_t r = r0 + i * 32; uint2 hi, lo;
            split4(ra[i], hi, lo);
            *(uint2*)(As + swz(r, c4 * 2)) = hi;
            *(uint2*)(As + swz(r, 16 + c4 * 2)) = lo;
            split4(rb[i], hi, lo);
            *(uint2*)(Bs + swz(r, c4 * 2)) = hi;
            *(uint2*)(Bs + swz(r, 16 + c4 * 2)) = lo;
        }
    }
    const int lr = lane >> 2, lw = lane & 3;

    for (int c = 0; c < nchunk; ++c) {
        if (c + 1 < nchunk) {
#pragma unroll
            for (int i = 0; i < 4; i++) {
                ra[i] = *(const float4*)(Ag + (c + 1) * 32 + i * strA);
                rb[i] = *(const float4*)(Bg + (c + 1) * 32 + i * strA);
            }
        }
        __syncthreads();
        uint32_t* As = smw + (c & 1) * 8192;
        uint32_t* Bs = As + 4096;
#pragma unroll
        for (int pass = 0; pass < 3; pass++) {
            const uint32_t aoff = (pass == 2) ? 16u : 0u;
            const uint32_t boff = (pass == 1) ? 16u : 0u;
#pragma unroll
            for (int s = 0; s < 2; s++) {
                const uint32_t kwa = aoff + s * 8 + lw;
                const uint32_t kwb = boff + s * 8 + lw;
                uint32_t bfr[4][2];
#pragma unroll
                for (int nt = 0; nt < 4; nt++) {
                    uint32_t n = wn * 32 + nt * 8 + lr;
                    bfr[nt][0] = Bs[swz(n, kwb)];
                    bfr[nt][1] = Bs[swz(n, kwb + 4)];
                }
#pragma unroll
                for (int mt = 0; mt < 4; mt++) {
                    uint32_t rr = wm * 64 + mt * 16 + lr;
                    uint32_t a0 = As[swz(rr, kwa)], a1 = As[swz(rr + 8, kwa)];
                    uint32_t a2 = As[swz(rr, kwa + 4)], a3 = As[swz(rr + 8, kwa + 4)];
#pragma unroll
                    for (int nt = 0; nt < 4; nt++)
                        mma16816(acc[mt][nt], a0, a1, a2, a3, bfr[nt][0], bfr[nt][1]);
                }
            }
        }
        if (c + 1 < nchunk) {
            uint32_t* An = smw + ((c + 1) & 1) * 8192;
            uint32_t* Bn = An + 4096;
#pragma unroll
            for (int i = 0; i < 4; i++) {
                uint32_t r = r0 + i * 32; uint2 hi, lo;
                split4(ra[i], hi, lo);
                *(uint2*)(An + swz(r, c4 * 2)) = hi;
                *(uint2*)(An + swz(r, 16 + c4 * 2)) = lo;
                split4(rb[i], hi, lo);
                *(uint2*)(Bn + swz(r, c4 * 2)) = hi;
                *(uint2*)(Bn + swz(r, 16 + c4 * 2)) = lo;
            }
        }
    }
#pragma unroll
    for (int mt = 0; mt < 4; mt++) {
        int row = bm + wm * 64 + mt * 16 + lr;
#pragma unroll
        for (int nt = 0; nt < 4; nt++) {
            int col = bn + wn * 32 + nt * 8 + lw * 2;
            float b0 = bias[col], b1 = bias[col + 1];
            *(float2*)(C + (size_t)row * N + col) =
                make_float2(acc[mt][nt][0] + b0, acc[mt][nt][1] + b1);
            *(float2*)(C + (size_t)(row + 8) * N + col) =
                make_float2(acc[mt][nt][2] + b0, acc[mt][nt][3] + b1);
        }
    }
}

__global__ void rope_kernel(float* __restrict__ data, int heads)
{
    int idx = blockIdx.x * blockDim.x + threadIdx.x;
    int total = BT * heads * 64;
    if (idx >= total) return;
    int d = idx & 63;
    int h = (idx >> 6) % heads;
    int row = idx / (heads * 64);
    float invf = powf(10000.0f, -(float)d / 64.0f);
    float ang = (float)h * invf;
    float c = cosf(ang), s = sinf(ang);
    float* p = data + (size_t)row * heads * 128 + h * 128;
    float x1 = p[d], x2 = p[d + 64];
    p[d] = x1 * c - x2 * s;
    p[d + 64] = x2 * c + x1 * s;
}

// ===== Tensor-core flash attention =====
#define QT_OFF 0
#define KT_OFF 16384
#define PT_OFF 24576
#define VH_OFF 32768
#define VL_OFF 37120
#define REDM_OFF 41472
#define REDS_OFF 41728
#define ATT_SMEM_BYTES (41984 * 4)

__global__ __launch_bounds__(256, 1) void attn_mma(
    const float* __restrict__ q, const float* __restrict__ k,
    const float* __restrict__ v, float* __restrict__ o)
{
    extern __shared__ uint32_t smu[];
    float* smf = (float*)smu;

    const int tid = threadIdx.x;
    const int wid = tid >> 5, lane = tid & 31;
    const int lr = lane >> 2, lw = lane & 3;
    const int wm = wid >> 1, wn = wid & 1;
    const int b = blockIdx.y >> 4, h = blockIdx.y & 15;
    const int kv = h >> 2;
    const int t0 = blockIdx.x * 128;
    const float scale = 0.08838834764831845f;
    const int r0 = tid >> 3, c4 = tid & 7;

    const size_t qgb = ((size_t)(b * 2048 + t0)) * CDIM + h * 128;
    const size_t kgb = ((size_t)(b * 2048)) * KVDIM + kv * 128;

    // prologue: Q (scaled+split), K(0), V(0)
#pragma unroll
    for (int c = 0; c < 4; c++)
#pragma unroll
        for (int i = 0; i < 4; i++) {
            int row = r0 + 32 * i;
            float4 val = *(const float4*)(q + qgb + (size_t)row * CDIM + c * 32 + c4 * 4);
            val.x *= scale; val.y *= scale; val.z *= scale; val.w *= scale;
            uint2 hi, lo; split4(val, hi, lo);
            uint32_t* Qb = smu + QT_OFF + c * 4096;
            *(uint2*)(Qb + swz(row, c4 * 2)) = hi;
            *(uint2*)(Qb + swz(row, 16 + c4 * 2)) = lo;
        }
#pragma unroll
    for (int c = 0; c < 4; c++)
#pragma unroll
        for (int i = 0; i < 2; i++) {
            int row = r0 + 32 * i;
            float4 val = *(const float4*)(k + kgb + (size_t)row * KVDIM + c * 32 + c4 * 4);
            uint2 hi, lo; split4(val, hi, lo);
            uint32_t* Kb = smu + KT_OFF + c * 2048;
            *(uint2*)(Kb + swz(row, c4 * 2)) = hi;
            *(uint2*)(Kb + swz(row, 16 + c4 * 2)) = lo;
        }
#pragma unroll
    for (int u = 0; u < 4; u++) {
        int idx = u * 256 + tid;
        int p = idx >> 5, d4 = idx & 31;
        const float* vb = v + kgb + (size_t)(2 * p) * KVDIM + d4 * 4;
        float4 v0 = *(const float4*)(vb);
        float4 v1 = *(const float4*)(vb + KVDIM);
        uint32_t hh[4], ll[4];
        pksplit(v0.x, v1.x, hh[0], ll[0]);
        pksplit(v0.y, v1.y, hh[1], ll[1]);
        pksplit(v0.z, v1.z, hh[2], ll[2]);
        pksplit(v0.w, v1.w, hh[3], ll[3]);
        *(uint4*)(smu + VH_OFF + p * 136 + d4 * 4) = make_uint4(hh[0], hh[1], hh[2], hh[3]);
        *(uint4*)(smu + VL_OFF + p * 136 + d4 * 4) = make_uint4(ll[0], ll[1], ll[2], ll[3]);
    }

    float accO[2][8][4];
#pragma unroll
    for (int mt = 0; mt < 2; mt++)
#pragma unroll
        for (int nt = 0; nt < 8; nt++)
#pragma unroll
            for (int e = 0; e < 4; e++) accO[mt][nt][e] = 0.0f;
    float m_s[2][2], l_s[2][2];
#pragma unroll
    for (int mt = 0; mt < 2; mt++) {
        m_s[mt][0] = -INFINITY; m_s[mt][1] = -INFINITY;
        l_s[mt][0] = 0.0f; l_s[mt][1] = 0.0f;
    }

    for (int ti = 0; ti < 32; ti++) {
        const int s0 = ti * 64;
        __syncthreads();

        // S = QK^T (3 passes via hi/lo fragments)
        float accS[2][4][4];
#pragma unroll
        for (int mt = 0; mt < 2; mt++)
#pragma unroll
            for (int nt = 0; nt < 4; nt++)
#pragma unroll
                for (int e = 0; e < 4; e++) accS[mt][nt][e] = 0.0f;
#pragma unroll
        for (int c = 0; c < 4; c++) {
            const uint32_t* Qb = smu + QT_OFF + c * 4096;
            const uint32_t* Kb = smu + KT_OFF + c * 2048;
#pragma unroll
            for (int s = 0; s < 2; s++) {
                const uint32_t kw = s * 8 + lw;
                uint32_t ah[2][4], al[2][4];
#pragma unroll
                for (int mt = 0; mt < 2; mt++) {
                    uint32_t rr = wm * 32 + mt * 16 + lr;
                    ah[mt][0] = Qb[swz(rr, kw)];       ah[mt][1] = Qb[swz(rr + 8, kw)];
                    ah[mt][2] = Qb[swz(rr, kw + 4)];   ah[mt][3] = Qb[swz(rr + 8, kw + 4)];
                    al[mt][0] = Qb[swz(rr, kw + 16)];  al[mt][1] = Qb[swz(rr + 8, kw + 16)];
                    al[mt][2] = Qb[swz(rr, kw + 20)];  al[mt][3] = Qb[swz(rr + 8, kw + 20)];
                }
                uint32_t bh[4][2], bl[4][2];
#pragma unroll
                for (int nt = 0; nt < 4; nt++) {
                    uint32_t n = wn * 32 + nt * 8 + lr;
                    bh[nt][0] = Kb[swz(n, kw)];      bh[nt][1] = Kb[swz(n, kw + 4)];
                    bl[nt][0] = Kb[swz(n, kw + 16)]; bl[nt][1] = Kb[swz(n, kw + 20)];
                }
#pragma unroll
                for (int mt = 0; mt < 2; mt++)
#pragma unroll
                    for (int nt = 0; nt < 4; nt++) {
                        mma16816(accS[mt][nt], ah[mt][0], ah[mt][1], ah[mt][2], ah[mt][3],
                                 bh[nt][0], bh[nt][1]);
                        mma16816(accS[mt][nt], ah[mt][0], ah[mt][1], ah[mt][2], ah[mt][3],
                                 bl[nt][0], bl[nt][1]);
                        mma16816(accS[mt][nt], al[mt][0], al[mt][1], al[mt][2], al[mt][3],
                                 bh[nt][0], bh[nt][1]);
                    }
            }
        }

        // prefetch next K/V
        float4 kr[8], vr0[4], vr1[4];
        const bool more = (ti + 1 < 32);
        if (more) {
            const int s0n = s0 + 64;
#pragma unroll
            for (int c = 0; c < 4; c++)
#pragma unroll
                for (int i = 0; i < 2; i++)
                    kr[c * 2 + i] = *(const float4*)(k + kgb +
                        (size_t)(s0n + r0 + 32 * i) * KVDIM + c * 32 + c4 * 4);
#pragma unroll
            for (int u = 0; u < 4; u++) {
                int idx = u * 256 + tid;
                int p = idx >> 5, d4 = idx & 31;
                const float* vb = v + kgb + (size_t)(s0n + 2 * p) * KVDIM + d4 * 4;
                vr0[u] = *(const float4*)(vb);
                vr1[u] = *(const float4*)(vb + KVDIM);
            }
        }

        // mask + online softmax
        {
            const int trow0 = t0 + wm * 32 + lr;
            float pmax[2][2];
#pragma unroll
            for (int mt = 0; mt < 2; mt++) {
                const int ta = trow0 + mt * 16, tb = ta + 8;
                float mx0 = -INFINITY, mx1 = -INFINITY;
#pragma unroll
                for (int nt = 0; nt < 4; nt++) {
                    const int sc = s0 + wn * 32 + nt * 8 + 2 * lw;
                    if (sc     <= ta) accS[mt][nt][0] += 1.0f;
                    if (sc + 1 <= ta) accS[mt][nt][1] += 1.0f;
                    if (sc     <= tb) accS[mt][nt][2] += 1.0f;
                    if (sc + 1 <= tb) accS[mt][nt][3] += 1.0f;
                    mx0 = fmaxf(mx0, fmaxf(accS[mt][nt][0], accS[mt][nt][1]));
                    mx1 = fmaxf(mx1, fmaxf(accS[mt][nt][2], accS[mt][nt][3]));
                }
                pmax[mt][0] = mx0; pmax[mt][1] = mx1;
            }
#pragma unroll
            for (int mt = 0; mt < 2; mt++)
#pragma unroll
                for (int hf = 0; hf < 2; hf++) {
                    float x = pmax[mt][hf];
                    x = fmaxf(x, __shfl_xor_sync(0xffffffffu, x, 1));
                    x = fmaxf(x, __shfl_xor_sync(0xffffffffu, x, 2));
                    pmax[mt][hf] = x;
                }
#pragma unroll
            for (int mt = 0; mt < 2; mt++) {
                int rowl = wm * 32 + mt * 16 + lr;
                smf[REDM_OFF + wn * 128 + rowl]     = pmax[mt][0];
                smf[REDM_OFF + wn * 128 + rowl + 8] = pmax[mt][1];
            }
            __syncthreads();
            float fac[2][2], mnew[2][2];
#pragma unroll
            for (int mt = 0; mt < 2; mt++)
#pragma unroll
                for (int hf = 0; hf < 2; hf++) {
                    int rowl = wm * 32 + mt * 16 + lr + hf * 8;
                    float full = fmaxf(pmax[mt][hf], smf[REDM_OFF + (wn ^ 1) * 128 + rowl]);
                    float mn = fmaxf(m_s[mt][hf], full);
                    fac[mt][hf] = fexp(m_s[mt][hf] - mn);
                    m_s[mt][hf] = mn;
                    mnew[mt][hf] = mn;
                }
#pragma unroll
            for (int mt = 0; mt < 2; mt++)
#pragma unroll
                for (int nt = 0; nt < 8; nt++) {
                    accO[mt][nt][0] *= fac[mt][0];
                    accO[mt][nt][1] *= fac[mt][0];
                    accO[mt][nt][2] *= fac[mt][1];
                    accO[mt][nt][3] *= fac[mt][1];
                }
            float psum[2][2] = {{0.0f, 0.0f}, {0.0f, 0.0f}};
#pragma unroll
            for (int mt = 0; mt < 2; mt++) {
                int rowl = wm * 32 + mt * 16 + lr;
#pragma unroll
                for (int nt = 0; nt < 4; nt++) {
                    float p0 = fexp(accS[mt][nt][0] - mnew[mt][0]);
                    float p1 = fexp(accS[mt][nt][1] - mnew[mt][0]);
                    float p2 = fexp(accS[mt][nt][2] - mnew[mt][1]);
                    float p3 = fexp(accS[mt][nt][3] - mnew[mt][1]);
                    psum[mt][0] += p0 + p1;
                    psum[mt][1] += p2 + p3;
                    uint32_t hi, lo;
                    uint32_t* Pb = smu + PT_OFF + wn * 4096;
                    pksplit(p0, p1, hi, lo);
                    Pb[swz(rowl, nt * 4 + lw)]      = hi;
                    Pb[swz(rowl, 16 + nt * 4 + lw)] = lo;
                    pksplit(p2, p3, hi, lo);
                    Pb[swz(rowl + 8, nt * 4 + lw)]      = hi;
                    Pb[swz(rowl + 8, 16 + nt * 4 + lw)] = lo;
                }
            }
#pragma unroll
            for (int mt = 0; mt < 2; mt++)
#pragma unroll
                for (int hf = 0; hf < 2; hf++) {
                    float x = psum[mt][hf];
                    x += __shfl_xor_sync(0xffffffffu, x, 1);
                    x += __shfl_xor_sync(0xffffffffu, x, 2);
                    psum[mt][hf] = x;
                }
#pragma unroll
            for (int mt = 0; mt < 2; mt++) {
                int rowl = wm * 32 + mt * 16 + lr;
                smf[REDS_OFF + wn * 128 + rowl]     = psum[mt][0];
                smf[REDS_OFF + wn * 128 + rowl + 8] = psum[mt][1];
            }
            __syncthreads();
#pragma unroll
            for (int mt = 0; mt < 2; mt++)
#pragma unroll
                for (int hf = 0; hf < 2; hf++) {
                    int rowl = wm * 32 + mt * 16 + lr + hf * 8;
                    l_s[mt][hf] = l_s[mt][hf] * fac[mt][hf] + psum[mt][hf]
                                + smf[REDS_OFF + (wn ^ 1) * 128 + rowl];
                }
        }

        // O += P @ V
#pragma unroll
        for (int ks = 0; ks < 4; ks++) {
            const uint32_t* Pb = smu + PT_OFF + (ks >> 1) * 4096;
            const uint32_t kw = (ks & 1) * 8 + lw;
            uint32_t ah[2][4], al[2][4];
#pragma unroll
            for (int mt = 0; mt < 2; mt++) {
                uint32_t rr = wm * 32 + mt * 16 + lr;
                ah[mt][0] = Pb[swz(rr, kw)];       ah[mt][1] = Pb[swz(rr + 8, kw)];
                ah[mt][2] = Pb[swz(rr, kw + 4)];   ah[mt][3] = Pb[swz(rr + 8, kw + 4)];
                al[mt][0] = Pb[swz(rr, kw + 16)];  al[mt][1] = Pb[swz(rr + 8, kw + 16)];
                al[mt][2] = Pb[swz(rr, kw + 20)];  al[mt][3] = Pb[swz(rr + 8, kw + 20)];
            }
            const uint32_t prow0 = (ks * 8 + lw) * 136;
            const uint32_t prow1 = (ks * 8 + lw + 4) * 136;
            uint32_t bh[8][2], bl[8][2];
#pragma unroll
            for (int nt = 0; nt < 8; nt++) {
                uint32_t dcol = wn * 64 + nt * 8 + lr;
                bh[nt][0] = smu[VH_OFF + prow0 + dcol];
                bh[nt][1] = smu[VH_OFF + prow1 + dcol];
                bl[nt][0] = smu[VL_OFF + prow0 + dcol];
                bl[nt][1] = smu[VL_OFF + prow1 + dcol];
            }
#pragma unroll
            for (int mt = 0; mt < 2; mt++)
#pragma unroll
                for (int nt = 0; nt < 8; nt++) {
                    mma16816(accO[mt][nt], ah[mt][0], ah[mt][1], ah[mt][2], ah[mt][3],
                             bh[nt][0], bh[nt][1]);
                    mma16816(accO[mt][nt], ah[mt][0], ah[mt][1], ah[mt][2], ah[mt][3],
                             bl[nt][0], bl[nt][1]);
                    mma16816(accO[mt][nt], al[mt][0], al[mt][1], al[mt][2], al[mt][3],
                             bh[nt][0], bh[nt][1]);
                }
        }

        __syncthreads();

        if (more) {
#pragma unroll
            for (int c = 0; c < 4; c++)
#pragma unroll
                for (int i = 0; i < 2; i++) {
                    int row = r0 + 32 * i;
                    uint2 hi, lo;
                    split4(kr[c * 2 + i], hi, lo);
                    uint32_t* Kb = smu + KT_OFF + c * 2048;
                    *(uint2*)(Kb + swz(row, c4 * 2)) = hi;
                    *(uint2*)(Kb + swz(row, 16 + c4 * 2)) = lo;
                }
#pragma unroll
            for (int u = 0; u < 4; u++) {
                int idx = u * 256 + tid;
                int p = idx >> 5, d4 = idx & 31;
                uint32_t hh[4], ll[4];
                pksplit(vr0[u].x, vr1[u].x, hh[0], ll[0]);
                pksplit(vr0[u].y, vr1[u].y, hh[1], ll[1]);
                pksplit(vr0[u].z, vr1[u].z, hh[2], ll[2]);
                pksplit(vr0[u].w, vr1[u].w, hh[3], ll[3]);
                *(uint4*)(smu + VH_OFF + p * 136 + d4 * 4) = make_uint4(hh[0], hh[1], hh[2], hh[3]);
                *(uint4*)(smu + VL_OFF + p * 136 + d4 * 4) = make_uint4(ll[0], ll[1], ll[2], ll[3]);
            }
        }
    }

    // epilogue
#pragma unroll
    for (int mt = 0; mt < 2; mt++) {
        float inv0 = 1.0f / l_s[mt][0];
        float inv1 = 1.0f / l_s[mt][1];
        int row = t0 + wm * 32 + mt * 16 + lr;
#pragma unroll
        for (int nt = 0; nt < 8; nt++) {
            int col = h * 128 + wn * 64 + nt * 8 + 2 * lw;
            *(float2*)(o + (size_t)(b * 2048 + row) * CDIM + col) =
                make_float2(accO[mt][nt][0] * inv0, accO[mt][nt][1] * inv0);
            *(float2*)(o + (size_t)(b * 2048 + row + 8) * CDIM + col) =
                make_float2(accO[mt][nt][2] * inv1, accO[mt][nt][3] * inv1);
        }
    }
}

extern "C" void kernel_launch(void* const* d_in, const int* in_sizes, int n_in,
                              void* d_out, int out_size)
{
    const float* x  = (const float*)d_in[0];
    const float* wq = (const float*)d_in[1];
    const float* bq = (const float*)d_in[2];
    const float* wk = (const float*)d_in[3];
    const float* bk = (const float*)d_in[4];
    const float* wv = (const float*)d_in[5];
    const float* bv = (const float*)d_in[6];
    const float* wo = (const float*)d_in[7];
    const float* bo = (const float*)d_in[8];
    float* out = (float*)d_out;

    float *qp, *kp, *vp, *ap;
    cudaGetSymbolAddress((void**)&qp, g_q);
    cudaGetSymbolAddress((void**)&kp, g_k);
    cudaGetSymbolAddress((void**)&vp, g_v);
    cudaGetSymbolAddress((void**)&ap, g_att);

    cudaFuncSetAttribute(gemm_mma,
                         cudaFuncAttributeMaxDynamicSharedMemorySize, GEMM_SMEM);
    cudaFuncSetAttribute(attn_mma,
                         cudaFuncAttributeMaxDynamicSharedMemorySize, ATT_SMEM_BYTES);

    gemm_mma<<<dim3(16, 32), 256, GEMM_SMEM>>>(x, wq, bq, qp, BT, CDIM, CDIM);
    gemm_mma<<<dim3(4, 32), 256, GEMM_SMEM>>>(x, wk, bk, kp, BT, KVDIM, CDIM);
    gemm_mma<<<dim3(4, 32), 256, GEMM_SMEM>>>(x, wv, bv, vp, BT, KVDIM, CDIM);

    rope_kernel<<<(BT * 16 * 64 + 255) / 256, 256>>>(qp, 16);
    rope_kernel<<<(BT * 4 * 64 + 255) / 256, 256>>>(kp, 4);

    attn_mma<<<dim3(16, 32), 256, ATT_SMEM_BYTES>>>(qp, kp, vp, ap);

    gemm_mma<<<dim3(16, 32), 256, GEMM_SMEM>>>(ap, wo, bo, out, BT, CDIM, CDIM);
}

// round 10
// speedup vs baseline: 1.7148x; 1.0709x over previous
#include <cuda_runtime.h>
#include <cuda_bf16.h>
#include <math.h>
#include <cstdint>

#define BT 4096
#define CDIM 2048
#define KVDIM 512

__device__ float g_q[(size_t)BT * CDIM];
__device__ float g_k[(size_t)BT * KVDIM];
__device__ float g_v[(size_t)BT * KVDIM];
__device__ float g_att[(size_t)BT * CDIM];

__device__ __forceinline__ void mma16816(
    float c[4], uint32_t a0, uint32_t a1, uint32_t a2, uint32_t a3,
    uint32_t b0, uint32_t b1)
{
    asm volatile(
        "mma.sync.aligned.m16n8k16.row.col.f32.bf16.bf16.f32 "
        "{%0,%1,%2,%3}, {%4,%5,%6,%7}, {%8,%9}, {%0,%1,%2,%3};"
        : "+f"(c[0]), "+f"(c[1]), "+f"(c[2]), "+f"(c[3])
        : "r"(a0), "r"(a1), "r"(a2), "r"(a3), "r"(b0), "r"(b1));
}

__device__ __forceinline__ void split4(float4 v, uint2& hi, uint2& lo) {
    __nv_bfloat16 hx = __float2bfloat16(v.x); float rx = v.x - __bfloat162float(hx);
    __nv_bfloat16 hy = __float2bfloat16(v.y); float ry = v.y - __bfloat162float(hy);
    __nv_bfloat16 hz = __float2bfloat16(v.z); float rz = v.z - __bfloat162float(hz);
    __nv_bfloat16 hw = __float2bfloat16(v.w); float rw = v.w - __bfloat162float(hw);
    hi.x = (uint32_t)__bfloat16_as_ushort(hx) | ((uint32_t)__bfloat16_as_ushort(hy) << 16);
    hi.y = (uint32_t)__bfloat16_as_ushort(hz) | ((uint32_t)__bfloat16_as_ushort(hw) << 16);
    lo.x = (uint32_t)__bfloat16_as_ushort(__float2bfloat16(rx))
         | ((uint32_t)__bfloat16_as_ushort(__float2bfloat16(ry)) << 16);
    lo.y = (uint32_t)__bfloat16_as_ushort(__float2bfloat16(rz))
         | ((uint32_t)__bfloat16_as_ushort(__float2bfloat16(rw)) << 16);
}

__device__ __forceinline__ void pksplit(float a, float b, uint32_t& hi, uint32_t& lo) {
    __nv_bfloat16 ha = __float2bfloat16(a), hb = __float2bfloat16(b);
    float ra = a - __bfloat162float(ha), rb = b - __bfloat162float(hb);
    hi = (uint32_t)__bfloat16_as_ushort(ha) | ((uint32_t)__bfloat16_as_ushort(hb) << 16);
    lo = (uint32_t)__bfloat16_as_ushort(__float2bfloat16(ra))
       | ((uint32_t)__bfloat16_as_ushort(__float2bfloat16(rb)) << 16);
}

__device__ __forceinline__ uint32_t swz(uint32_t r, uint32_t w) {
    return r * 32u + (w ^ ((r & 7u) << 2));
}

// exp for x<=0 on FMA pipe
__device__ __forceinline__ float fexp(float x) {
    float t = fmaxf(x * 1.4426950408889634f, -126.0f);
    float r = rintf(t);
    float u = (t - r) * 0.6931471805599453f;
    float p = 0.008333333333f;
    p = fmaf(p, u, 0.041666666667f);
    p = fmaf(p, u, 0.166666666667f);
    p = fmaf(p, u, 0.5f);
    p = fmaf(p, u, 1.0f);
    p = fmaf(p, u, 1.0f);
    return p * __int_as_float(((int)r + 127) << 23);
}

// ===== GEMM (unchanged, passing) =====
#define GEMM_SMEM (4 * 16384)

__global__ __launch_bounds__(256) void gemm_mma(
    const float* __restrict__ A, const float* __restrict__ B,
    const float* __restrict__ bias, float* __restrict__ C,
    int M, int N, int K)
{
    extern __shared__ uint32_t smw[];
    const int tid = threadIdx.x;
    const int wid = tid >> 5, lane = tid & 31;
    const int bm = blockIdx.y * 128, bn = blockIdx.x * 128;
    const int wm = wid >> 2, wn = wid & 3;
    const int r0 = tid >> 3, c4 = tid & 7;
    const float* Ag = A + (size_t)(bm + r0) * K + c4 * 4;
    const float* Bg = B + (size_t)(bn + r0) * K + c4 * 4;
    const size_t strA = (size_t)32 * K;
    const int nchunk = K >> 5;

    float acc[4][4][4];
#pragma unroll
    for (int mt = 0; mt < 4; mt++)
#pragma unroll
        for (int nt = 0; nt < 4; nt++)
#pragma unroll
            for (int e = 0; e < 4; e++) acc[mt][nt][e] = 0.0f;

    float4 ra[4], rb[4];
#pragma unroll
    for (int i = 0; i < 4; i++) {
        ra[i] = *(const float4*)(Ag + i * strA);
        rb[i] = *(const float4*)(Bg + i * strA);
    }
    {
        uint32_t* As = smw; uint32_t* Bs = smw + 4096;
#pragma unroll
        for (int i = 0; i < 4; i++) {
            uint32_t r = r0 + i * 32; uint2 hi, lo;
            split4(ra[i], hi, lo);
            *(uint2*)(As + swz(r, c4 * 2)) = hi;
            *(uint2*)(As + swz(r, 16 + c4 * 2)) = lo;
            split4(rb[i], hi, lo);
            *(uint2*)(Bs + swz(r, c4 * 2)) = hi;
            *(uint2*)(Bs + swz(r, 16 + c4 * 2)) = lo;
        }
    }
    const int lr = lane >> 2, lw = lane & 3;

    for (int c = 0; c < nchunk; ++c) {
        if (c + 1 < nchunk) {
#pragma unroll
            for (int i = 0; i < 4; i++) {
                ra[i] = *(const float4*)(Ag + (c + 1) * 32 + i * strA);
                rb[i] = *(const float4*)(Bg + (c + 1) * 32 + i * strA);
            }
        }
        __syncthreads();
        uint32_t* As = smw + (c & 1) * 8192;
        uint32_t* Bs = As + 4096;
#pragma unroll
        for (int pass = 0; pass < 3; pass++) {
            const uint32_t aoff = (pass == 2) ? 16u : 0u;
            const uint32_t boff = (pass == 1) ? 16u : 0u;
#pragma unroll
            for (int s = 0; s < 2; s++) {
                const uint32_t kwa = aoff + s * 8 + lw;
                const uint32_t kwb = boff + s * 8 + lw;
                uint32_t bfr[4][2];
#pragma unroll
                for (int nt = 0; nt < 4; nt++) {
                    uint32_t n = wn * 32 + nt * 8 + lr;
                    bfr[nt][0] = Bs[swz(n, kwb)];
                    bfr[nt][1] = Bs[swz(n, kwb + 4)];
                }
#pragma unroll
                for (int mt = 0; mt < 4; mt++) {
                    uint32_t rr = wm * 64 + mt * 16 + lr;
                    uint32_t a0 = As[swz(rr, kwa)], a1 = As[swz(rr + 8, kwa)];
                    uint32_t a2 = As[swz(rr, kwa + 4)], a3 = As[swz(rr + 8, kwa + 4)];
#pragma unroll
                    for (int nt = 0; nt < 4; nt++)
                        mma16816(acc[mt][nt], a0, a1, a2, a3, bfr[nt][0], bfr[nt][1]);
                }
            }
        }
        if (c + 1 < nchunk) {
            uint32_t* An = smw + ((c + 1) & 1) * 8192;
            uint32_t* Bn = An + 4096;
#pragma unroll
            for (int i = 0; i < 4; i++) {
                uint32_t r = r0 + i * 32; uint2 hi, lo;
                split4(ra[i], hi, lo);
                *(uint2*)(An + swz(r, c4 * 2)) = hi;
                *(uint2*)(An + swz(r, 16 + c4 * 2)) = lo;
                split4(rb[i], hi, lo);
                *(uint2*)(Bn + swz(r, c4 * 2)) = hi;
                *(uint2*)(Bn + swz(r, 16 + c4 * 2)) = lo;
            }
        }
    }
#pragma unroll
    for (int mt = 0; mt < 4; mt++) {
        int row = bm + wm * 64 + mt * 16 + lr;
#pragma unroll
        for (int nt = 0; nt < 4; nt++) {
            int col = bn + wn * 32 + nt * 8 + lw * 2;
            float b0 = bias[col], b1 = bias[col + 1];
            *(float2*)(C + (size_t)row * N + col) =
                make_float2(acc[mt][nt][0] + b0, acc[mt][nt][1] + b1);
            *(float2*)(C + (size_t)(row + 8) * N + col) =
                make_float2(acc[mt][nt][2] + b0, acc[mt][nt][3] + b1);
        }
    }
}

__global__ void rope_kernel(float* __restrict__ data, int heads)
{
    int idx = blockIdx.x * blockDim.x + threadIdx.x;
    int total = BT * heads * 64;
    if (idx >= total) return;
    int d = idx & 63;
    int h = (idx >> 6) % heads;
    int row = idx / (heads * 64);
    float invf = powf(10000.0f, -(float)d / 64.0f);
    float ang = (float)h * invf;
    float c = cosf(ang), s = sinf(ang);
    float* p = data + (size_t)row * heads * 128 + h * 128;
    float x1 = p[d], x2 = p[d + 64];
    p[d] = x1 * c - x2 * s;
    p[d + 64] = x2 * c + x1 * s;
}

// ===== Tensor-core flash attention, P register-resident (FA2 style) =====
#define QT_OFF 0
#define KT_OFF 16384
#define VH_OFF 24576
#define VL_OFF 28928
#define ATT_SMEM_BYTES (33280 * 4)

__global__ __launch_bounds__(256, 1) void attn_mma(
    const float* __restrict__ q, const float* __restrict__ k,
    const float* __restrict__ v, float* __restrict__ o)
{
    extern __shared__ uint32_t smu[];

    const int tid = threadIdx.x;
    const int wid = tid >> 5, lane = tid & 31;
    const int lr = lane >> 2, lw = lane & 3;
    const int b = blockIdx.y >> 4, h = blockIdx.y & 15;
    const int kv = h >> 2;
    const int t0 = blockIdx.x * 128;
    const float scale = 0.08838834764831845f;
    const int r0 = tid >> 3, c4 = tid & 7;

    const size_t qgb = ((size_t)(b * 2048 + t0)) * CDIM + h * 128;
    const size_t kgb = ((size_t)(b * 2048)) * KVDIM + kv * 128;

    // prologue: Q (scaled+split), K(0), V(0)
#pragma unroll
    for (int c = 0; c < 4; c++)
#pragma unroll
        for (int i = 0; i < 4; i++) {
            int row = r0 + 32 * i;
            float4 val = *(const float4*)(q + qgb + (size_t)row * CDIM + c * 32 + c4 * 4);
            val.x *= scale; val.y *= scale; val.z *= scale; val.w *= scale;
            uint2 hi, lo; split4(val, hi, lo);
            uint32_t* Qb = smu + QT_OFF + c * 4096;
            *(uint2*)(Qb + swz(row, c4 * 2)) = hi;
            *(uint2*)(Qb + swz(row, 16 + c4 * 2)) = lo;
        }
#pragma unroll
    for (int c = 0; c < 4; c++)
#pragma unroll
        for (int i = 0; i < 2; i++) {
            int row = r0 + 32 * i;
            float4 val = *(const float4*)(k + kgb + (size_t)row * KVDIM + c * 32 + c4 * 4);
            uint2 hi, lo; split4(val, hi, lo);
            uint32_t* Kb = smu + KT_OFF + c * 2048;
            *(uint2*)(Kb + swz(row, c4 * 2)) = hi;
            *(uint2*)(Kb + swz(row, 16 + c4 * 2)) = lo;
        }
#pragma unroll
    for (int u = 0; u < 4; u++) {
        int idx = u * 256 + tid;
        int p = idx >> 5, d4 = idx & 31;
        const float* vb = v + kgb + (size_t)(2 * p) * KVDIM + d4 * 4;
        float4 v0 = *(const float4*)(vb);
        float4 v1 = *(const float4*)(vb + KVDIM);
        uint32_t hh[4], ll[4];
        pksplit(v0.x, v1.x, hh[0], ll[0]);
        pksplit(v0.y, v1.y, hh[1], ll[1]);
        pksplit(v0.z, v1.z, hh[2], ll[2]);
        pksplit(v0.w, v1.w, hh[3], ll[3]);
        *(uint4*)(smu + VH_OFF + p * 136 + d4 * 4) = make_uint4(hh[0], hh[1], hh[2], hh[3]);
        *(uint4*)(smu + VL_OFF + p * 136 + d4 * 4) = make_uint4(ll[0], ll[1], ll[2], ll[3]);
    }

    float accO[16][4];
#pragma unroll
    for (int nt = 0; nt < 16; nt++)
#pragma unroll
        for (int e = 0; e < 4; e++) accO[nt][e] = 0.0f;
    float m_s[2] = {-INFINITY, -INFINITY};
    float l_s[2] = {0.0f, 0.0f};

    for (int ti = 0; ti < 32; ti++) {
        const int s0 = ti * 64;
        __syncthreads();   // K/V tiles ready

        // ---- S = QK^T: warp owns rows [wid*16, +16), full 64 keys ----
        float accS[8][4];
#pragma unroll
        for (int nt = 0; nt < 8; nt++)
#pragma unroll
            for (int e = 0; e < 4; e++) accS[nt][e] = 0.0f;
#pragma unroll
        for (int c = 0; c < 4; c++) {
            const uint32_t* Qb = smu + QT_OFF + c * 4096;
            const uint32_t* Kb = smu + KT_OFF + c * 2048;
#pragma unroll
            for (int s = 0; s < 2; s++) {
                const uint32_t kw = s * 8 + lw;
                const uint32_t rr = wid * 16 + lr;
                uint32_t ah0 = Qb[swz(rr, kw)],      ah1 = Qb[swz(rr + 8, kw)];
                uint32_t ah2 = Qb[swz(rr, kw + 4)],  ah3 = Qb[swz(rr + 8, kw + 4)];
                uint32_t al0 = Qb[swz(rr, kw + 16)], al1 = Qb[swz(rr + 8, kw + 16)];
                uint32_t al2 = Qb[swz(rr, kw + 20)], al3 = Qb[swz(rr + 8, kw + 20)];
#pragma unroll
                for (int nt = 0; nt < 8; nt++) {
                    uint32_t n = nt * 8 + lr;
                    uint32_t bh0 = Kb[swz(n, kw)],      bh1 = Kb[swz(n, kw + 4)];
                    uint32_t bl0 = Kb[swz(n, kw + 16)], bl1 = Kb[swz(n, kw + 20)];
                    mma16816(accS[nt], ah0, ah1, ah2, ah3, bh0, bh1);
                    mma16816(accS[nt], ah0, ah1, ah2, ah3, bl0, bl1);
                    mma16816(accS[nt], al0, al1, al2, al3, bh0, bh1);
                }
            }
        }

        // ---- mask + warp-local online softmax; P -> registers ----
        uint32_t ph[4][4], pl[4][4];
        {
            const int ta = t0 + wid * 16 + lr;
            const int tb = ta + 8;
            float mx0 = -INFINITY, mx1 = -INFINITY;
#pragma unroll
            for (int nt = 0; nt < 8; nt++) {
                const int sc = s0 + nt * 8 + 2 * lw;
                if (sc     <= ta) accS[nt][0] += 1.0f;
                if (sc + 1 <= ta) accS[nt][1] += 1.0f;
                if (sc     <= tb) accS[nt][2] += 1.0f;
                if (sc + 1 <= tb) accS[nt][3] += 1.0f;
                mx0 = fmaxf(mx0, fmaxf(accS[nt][0], accS[nt][1]));
                mx1 = fmaxf(mx1, fmaxf(accS[nt][2], accS[nt][3]));
            }
            mx0 = fmaxf(mx0, __shfl_xor_sync(0xffffffffu, mx0, 1));
            mx0 = fmaxf(mx0, __shfl_xor_sync(0xffffffffu, mx0, 2));
            mx1 = fmaxf(mx1, __shfl_xor_sync(0xffffffffu, mx1, 1));
            mx1 = fmaxf(mx1, __shfl_xor_sync(0xffffffffu, mx1, 2));
            float mn0 = fmaxf(m_s[0], mx0);
            float mn1 = fmaxf(m_s[1], mx1);
            float fac0 = fexp(m_s[0] - mn0);
            float fac1 = fexp(m_s[1] - mn1);
            m_s[0] = mn0; m_s[1] = mn1;
#pragma unroll
            for (int nt = 0; nt < 16; nt++) {
                accO[nt][0] *= fac0; accO[nt][1] *= fac0;
                accO[nt][2] *= fac1; accO[nt][3] *= fac1;
            }
            float sum0 = 0.0f, sum1 = 0.0f;
#pragma unroll
            for (int nt = 0; nt < 8; nt++) {
                float p0 = fexp(accS[nt][0] - mn0);
                float p1 = fexp(accS[nt][1] - mn0);
                float p2 = fexp(accS[nt][2] - mn1);
                float p3 = fexp(accS[nt][3] - mn1);
                sum0 += p0 + p1;
                sum1 += p2 + p3;
                int kt = nt >> 1, e0 = (nt & 1) * 2;
                pksplit(p0, p1, ph[kt][e0],     pl[kt][e0]);
                pksplit(p2, p3, ph[kt][e0 + 1], pl[kt][e0 + 1]);
            }
            sum0 += __shfl_xor_sync(0xffffffffu, sum0, 1);
            sum0 += __shfl_xor_sync(0xffffffffu, sum0, 2);
            sum1 += __shfl_xor_sync(0xffffffffu, sum1, 1);
            sum1 += __shfl_xor_sync(0xffffffffu, sum1, 2);
            l_s[0] = l_s[0] * fac0 + sum0;
            l_s[1] = l_s[1] * fac1 + sum1;
        }

        // ---- prefetch next K/V (hidden under PV MMAs) ----
        float4 kr[8], vr0[4], vr1[4];
        const bool more = (ti + 1 < 32);
        if (more) {
            const int s0n = s0 + 64;
#pragma unroll
            for (int c = 0; c < 4; c++)
#pragma unroll
                for (int i = 0; i < 2; i++)
                    kr[c * 2 + i] = *(const float4*)(k + kgb +
                        (size_t)(s0n + r0 + 32 * i) * KVDIM + c * 32 + c4 * 4);
#pragma unroll
            for (int u = 0; u < 4; u++) {
                int idx = u * 256 + tid;
                int p = idx >> 5, d4 = idx & 31;
                const float* vb = v + kgb + (size_t)(s0n + 2 * p) * KVDIM + d4 * 4;
                vr0[u] = *(const float4*)(vb);
                vr1[u] = *(const float4*)(vb + KVDIM);
            }
        }

        // ---- O += P @ V (P in registers; warp covers full d=128) ----
#pragma unroll
        for (int ks = 0; ks < 4; ks++) {
            const uint32_t prow0 = (ks * 8 + lw) * 136;
            const uint32_t prow1 = (ks * 8 + lw + 4) * 136;
#pragma unroll
            for (int nt = 0; nt < 16; nt++) {
                uint32_t dcol = nt * 8 + lr;
                uint32_t vh0 = smu[VH_OFF + prow0 + dcol];
                uint32_t vh1 = smu[VH_OFF + prow1 + dcol];
                uint32_t vl0 = smu[VL_OFF + prow0 + dcol];
                uint32_t vl1 = smu[VL_OFF + prow1 + dcol];
                mma16816(accO[nt], ph[ks][0], ph[ks][1], ph[ks][2], ph[ks][3], vh0, vh1);
                mma16816(accO[nt], ph[ks][0], ph[ks][1], ph[ks][2], ph[ks][3], vl0, vl1);
                mma16816(accO[nt], pl[ks][0], pl[ks][1], pl[ks][2], pl[ks][3], vh0, vh1);
            }
        }

        __syncthreads();   // done reading K/V before overwrite

        if (more) {
#pragma unroll
            for (int c = 0; c < 4; c++)
#pragma unroll
                for (int i = 0; i < 2; i++) {
                    int row = r0 + 32 * i;
                    uint2 hi, lo;
                    split4(kr[c * 2 + i], hi, lo);
                    uint32_t* Kb = smu + KT_OFF + c * 2048;
                    *(uint2*)(Kb + swz(row, c4 * 2)) = hi;
                    *(uint2*)(Kb + swz(row, 16 + c4 * 2)) = lo;
                }
#pragma unroll
            for (int u = 0; u < 4; u++) {
                int idx = u * 256 + tid;
                int p = idx >> 5, d4 = idx & 31;
                uint32_t hh[4], ll[4];
                pksplit(vr0[u].x, vr1[u].x, hh[0], ll[0]);
                pksplit(vr0[u].y, vr1[u].y, hh[1], ll[1]);
                pksplit(vr0[u].z, vr1[u].z, hh[2], ll[2]);
                pksplit(vr0[u].w, vr1[u].w, hh[3], ll[3]);
                *(uint4*)(smu + VH_OFF + p * 136 + d4 * 4) = make_uint4(hh[0], hh[1], hh[2], hh[3]);
                *(uint4*)(smu + VL_OFF + p * 136 + d4 * 4) = make_uint4(ll[0], ll[1], ll[2], ll[3]);
            }
        }
    }

    // epilogue
    {
        float inv0 = 1.0f / l_s[0];
        float inv1 = 1.0f / l_s[1];
        int row = t0 + wid * 16 + lr;
#pragma unroll
        for (int nt = 0; nt < 16; nt++) {
            int col = h * 128 + nt * 8 + 2 * lw;
            *(float2*)(o + (size_t)(b * 2048 + row) * CDIM + col) =
                make_float2(accO[nt][0] * inv0, accO[nt][1] * inv0);
            *(float2*)(o + (size_t)(b * 2048 + row + 8) * CDIM + col) =
                make_float2(accO[nt][2] * inv1, accO[nt][3] * inv1);
        }
    }
}

extern "C" void kernel_launch(void* const* d_in, const int* in_sizes, int n_in,
                              void* d_out, int out_size)
{
    const float* x  = (const float*)d_in[0];
    const float* wq = (const float*)d_in[1];
    const float* bq = (const float*)d_in[2];
    const float* wk = (const float*)d_in[3];
    const float* bk = (const float*)d_in[4];
    const float* wv = (const float*)d_in[5];
    const float* bv = (const float*)d_in[6];
    const float* wo = (const float*)d_in[7];
    const float* bo = (const float*)d_in[8];
    float* out = (float*)d_out;

    float *qp, *kp, *vp, *ap;
    cudaGetSymbolAddress((void**)&qp, g_q);
    cudaGetSymbolAddress((void**)&kp, g_k);
    cudaGetSymbolAddress((void**)&vp, g_v);
    cudaGetSymbolAddress((void**)&ap, g_att);

    cudaFuncSetAttribute(gemm_mma,
                         cudaFuncAttributeMaxDynamicSharedMemorySize, GEMM_SMEM);
    cudaFuncSetAttribute(attn_mma,
                         cudaFuncAttributeMaxDynamicSharedMemorySize, ATT_SMEM_BYTES);

    gemm_mma<<<dim3(16, 32), 256, GEMM_SMEM>>>(x, wq, bq, qp, BT, CDIM, CDIM);
    gemm_mma<<<dim3(4, 32), 256, GEMM_SMEM>>>(x, wk, bk, kp, BT, KVDIM, CDIM);
    gemm_mma<<<dim3(4, 32), 256, GEMM_SMEM>>>(x, wv, bv, vp, BT, KVDIM, CDIM);

    rope_kernel<<<(BT * 16 * 64 + 255) / 256, 256>>>(qp, 16);
    rope_kernel<<<(BT * 4 * 64 + 255) / 256, 256>>>(kp, 4);

    attn_mma<<<dim3(16, 32), 256, ATT_SMEM_BYTES>>>(qp, kp, vp, ap);

    gemm_mma<<<dim3(16, 32), 256, GEMM_SMEM>>>(ap, wo, bo, out, BT, CDIM, CDIM);
}

// round 13
// speedup vs baseline: 2.1431x; 1.2498x over previous
#include <cuda_runtime.h>
#include <cuda_bf16.h>
#include <cuda_fp16.h>
#include <math.h>
#include <cstdint>
#include <cstring>

#define BT 4096
#define CDIM 2048
#define KVDIM 512

__device__ float g_q[(size_t)BT * CDIM];
__device__ float g_k[(size_t)BT * KVDIM];
__device__ float g_v[(size_t)BT * KVDIM];
__device__ float g_att[(size_t)BT * CDIM];

// bf16 mma (GEMM path)
__device__ __forceinline__ void mma16816(
    float c[4], uint32_t a0, uint32_t a1, uint32_t a2, uint32_t a3,
    uint32_t b0, uint32_t b1)
{
    asm volatile(
        "mma.sync.aligned.m16n8k16.row.col.f32.bf16.bf16.f32 "
        "{%0,%1,%2,%3}, {%4,%5,%6,%7}, {%8,%9}, {%0,%1,%2,%3};"
        : "+f"(c[0]), "+f"(c[1]), "+f"(c[2]), "+f"(c[3])
        : "r"(a0), "r"(a1), "r"(a2), "r"(a3), "r"(b0), "r"(b1));
}

// fp16 mma (attention path)
__device__ __forceinline__ void mma16816h(
    float c[4], uint32_t a0, uint32_t a1, uint32_t a2, uint32_t a3,
    uint32_t b0, uint32_t b1)
{
    asm volatile(
        "mma.sync.aligned.m16n8k16.row.col.f32.f16.f16.f32 "
        "{%0,%1,%2,%3}, {%4,%5,%6,%7}, {%8,%9}, {%0,%1,%2,%3};"
        : "+f"(c[0]), "+f"(c[1]), "+f"(c[2]), "+f"(c[3])
        : "r"(a0), "r"(a1), "r"(a2), "r"(a3), "r"(b0), "r"(b1));
}

__device__ __forceinline__ void split4(float4 v, uint2& hi, uint2& lo) {
    __nv_bfloat16 hx = __float2bfloat16(v.x); float rx = v.x - __bfloat162float(hx);
    __nv_bfloat16 hy = __float2bfloat16(v.y); float ry = v.y - __bfloat162float(hy);
    __nv_bfloat16 hz = __float2bfloat16(v.z); float rz = v.z - __bfloat162float(hz);
    __nv_bfloat16 hw = __float2bfloat16(v.w); float rw = v.w - __bfloat162float(hw);
    hi.x = (uint32_t)__bfloat16_as_ushort(hx) | ((uint32_t)__bfloat16_as_ushort(hy) << 16);
    hi.y = (uint32_t)__bfloat16_as_ushort(hz) | ((uint32_t)__bfloat16_as_ushort(hw) << 16);
    lo.x = (uint32_t)__bfloat16_as_ushort(__float2bfloat16(rx))
         | ((uint32_t)__bfloat16_as_ushort(__float2bfloat16(ry)) << 16);
    lo.y = (uint32_t)__bfloat16_as_ushort(__float2bfloat16(rz))
         | ((uint32_t)__bfloat16_as_ushort(__float2bfloat16(rw)) << 16);
}

// pack two floats into one fp16x2 word (a in low half)
__device__ __forceinline__ uint32_t pkh(float a, float b) {
    __half2 h = __floats2half2_rn(a, b);
    uint32_t r;
    memcpy(&r, &h, 4);
    return r;
}

__device__ __forceinline__ uint32_t swz(uint32_t r, uint32_t w) {
    return r * 32u + (w ^ ((r & 7u) << 2));
}

// exp for x<=0 on FMA pipe
__device__ __forceinline__ float fexp(float x) {
    float t = fmaxf(x * 1.4426950408889634f, -126.0f);
    float r = rintf(t);
    float u = (t - r) * 0.6931471805599453f;
    float p = 0.008333333333f;
    p = fmaf(p, u, 0.041666666667f);
    p = fmaf(p, u, 0.166666666667f);
    p = fmaf(p, u, 0.5f);
    p = fmaf(p, u, 1.0f);
    p = fmaf(p, u, 1.0f);
    return p * __int_as_float(((int)r + 127) << 23);
}

// ===== GEMM (bf16 3-pass, unchanged, passing) =====
#define GEMM_SMEM (4 * 16384)

__global__ __launch_bounds__(256) void gemm_mma(
    const float* __restrict__ A, const float* __restrict__ B,
    const float* __restrict__ bias, float* __restrict__ C,
    int M, int N, int K)
{
    extern __shared__ uint32_t smw[];
    const int tid = threadIdx.x;
    const int wid = tid >> 5, lane = tid & 31;
    const int bm = blockIdx.y * 128, bn = blockIdx.x * 128;
    const int wm = wid >> 2, wn = wid & 3;
    const int r0 = tid >> 3, c4 = tid & 7;
    const float* Ag = A + (size_t)(bm + r0) * K + c4 * 4;
    const float* Bg = B + (size_t)(bn + r0) * K + c4 * 4;
    const size_t strA = (size_t)32 * K;
    const int nchunk = K >> 5;

    float acc[4][4][4];
#pragma unroll
    for (int mt = 0; mt < 4; mt++)
#pragma unroll
        for (int nt = 0; nt < 4; nt++)
#pragma unroll
            for (int e = 0; e < 4; e++) acc[mt][nt][e] = 0.0f;

    float4 ra[4], rb[4];
#pragma unroll
    for (int i = 0; i < 4; i++) {
        ra[i] = *(const float4*)(Ag + i * strA);
        rb[i] = *(const float4*)(Bg + i * strA);
    }
    {
        uint32_t* As = smw; uint32_t* Bs = smw + 4096;
#pragma unroll
        for (int i = 0; i < 4; i++) {
            uint32_t r = r0 + i * 32; uint2 hi, lo;
            split4(ra[i], hi, lo);
            *(uint2*)(As + swz(r, c4 * 2)) = hi;
            *(uint2*)(As + swz(r, 16 + c4 * 2)) = lo;
            split4(rb[i], hi, lo);
            *(uint2*)(Bs + swz(r, c4 * 2)) = hi;
            *(uint2*)(Bs + swz(r, 16 + c4 * 2)) = lo;
        }
    }
    const int lr = lane >> 2, lw = lane & 3;

    for (int c = 0; c < nchunk; ++c) {
        if (c + 1 < nchunk) {
#pragma unroll
            for (int i = 0; i < 4; i++) {
                ra[i] = *(const float4*)(Ag + (c + 1) * 32 + i * strA);
                rb[i] = *(const float4*)(Bg + (c + 1) * 32 + i * strA);
            }
        }
        __syncthreads();
        uint32_t* As = smw + (c & 1) * 8192;
        uint32_t* Bs = As + 4096;
#pragma unroll
        for (int pass = 0; pass < 3; pass++) {
            const uint32_t aoff = (pass == 2) ? 16u : 0u;
            const uint32_t boff = (pass == 1) ? 16u : 0u;
#pragma unroll
            for (int s = 0; s < 2; s++) {
                const uint32_t kwa = aoff + s * 8 + lw;
                const uint32_t kwb = boff + s * 8 + lw;
                uint32_t bfr[4][2];
#pragma unroll
                for (int nt = 0; nt < 4; nt++) {
                    uint32_t n = wn * 32 + nt * 8 + lr;
                    bfr[nt][0] = Bs[swz(n, kwb)];
                    bfr[nt][1] = Bs[swz(n, kwb + 4)];
                }
#pragma unroll
                for (int mt = 0; mt < 4; mt++) {
                    uint32_t rr = wm * 64 + mt * 16 + lr;
                    uint32_t a0 = As[swz(rr, kwa)], a1 = As[swz(rr + 8, kwa)];
                    uint32_t a2 = As[swz(rr, kwa + 4)], a3 = As[swz(rr + 8, kwa + 4)];
#pragma unroll
                    for (int nt = 0; nt < 4; nt++)
                        mma16816(acc[mt][nt], a0, a1, a2, a3, bfr[nt][0], bfr[nt][1]);
                }
            }
        }
        if (c + 1 < nchunk) {
            uint32_t* An = smw + ((c + 1) & 1) * 8192;
            uint32_t* Bn = An + 4096;
#pragma unroll
            for (int i = 0; i < 4; i++) {
                uint32_t r = r0 + i * 32; uint2 hi, lo;
                split4(ra[i], hi, lo);
                *(uint2*)(An + swz(r, c4 * 2)) = hi;
                *(uint2*)(An + swz(r, 16 + c4 * 2)) = lo;
                split4(rb[i], hi, lo);
                *(uint2*)(Bn + swz(r, c4 * 2)) = hi;
                *(uint2*)(Bn + swz(r, 16 + c4 * 2)) = lo;
            }
        }
    }
#pragma unroll
    for (int mt = 0; mt < 4; mt++) {
        int row = bm + wm * 64 + mt * 16 + lr;
#pragma unroll
        for (int nt = 0; nt < 4; nt++) {
            int col = bn + wn * 32 + nt * 8 + lw * 2;
            float b0 = bias[col], b1 = bias[col + 1];
            *(float2*)(C + (size_t)row * N + col) =
                make_float2(acc[mt][nt][0] + b0, acc[mt][nt][1] + b1);
            *(float2*)(C + (size_t)(row + 8) * N + col) =
                make_float2(acc[mt][nt][2] + b0, acc[mt][nt][3] + b1);
        }
    }
}

__global__ void rope_kernel(float* __restrict__ data, int heads)
{
    int idx = blockIdx.x * blockDim.x + threadIdx.x;
    int total = BT * heads * 64;
    if (idx >= total) return;
    int d = idx & 63;
    int h = (idx >> 6) % heads;
    int row = idx / (heads * 64);
    float invf = powf(10000.0f, -(float)d / 64.0f);
    float ang = (float)h * invf;
    float c = cosf(ang), s = sinf(ang);
    float* p = data + (size_t)row * heads * 128 + h * 128;
    float x1 = p[d], x2 = p[d + 64];
    p[d] = x1 * c - x2 * s;
    p[d + 64] = x2 * c + x1 * s;
}

// ===== fp16 single-pass flash attention, Q fragments register-resident =====
// smem (words): Q 2x[128][32] = 8192 | K 2x[64][32] = 4096 | V 32x136 = 4352
#define QT_OFF 0
#define KT_OFF 8192
#define VF_OFF 12288
#define ATT_SMEM_BYTES (16640 * 4)

__global__ __launch_bounds__(256, 1) void attn_mma(
    const float* __restrict__ q, const float* __restrict__ k,
    const float* __restrict__ v, float* __restrict__ o)
{
    extern __shared__ uint32_t smu[];

    const int tid = threadIdx.x;
    const int wid = tid >> 5, lane = tid & 31;
    const int lr = lane >> 2, lw = lane & 3;
    const int b = blockIdx.y >> 4, h = blockIdx.y & 15;
    const int kv = h >> 2;
    const int t0 = blockIdx.x * 128;
    const float scale = 0.08838834764831845f;
    const int r0 = tid >> 3, c4 = tid & 7;

    const size_t qgb = ((size_t)(b * 2048 + t0)) * CDIM + h * 128;
    const size_t kgb = ((size_t)(b * 2048)) * KVDIM + kv * 128;

    // ---- prologue: Q (scaled -> fp16), K(0), V(0) ----
#pragma unroll
    for (int c = 0; c < 2; c++)
#pragma unroll
        for (int i = 0; i < 4; i++) {
            int row = r0 + 32 * i;
            const float* src = q + qgb + (size_t)row * CDIM + c * 64 + c4 * 8;
            float4 v0 = *(const float4*)(src);
            float4 v1 = *(const float4*)(src + 4);
            uint4 w;
            w.x = pkh(v0.x * scale, v0.y * scale);
            w.y = pkh(v0.z * scale, v0.w * scale);
            w.z = pkh(v1.x * scale, v1.y * scale);
            w.w = pkh(v1.z * scale, v1.w * scale);
            *(uint4*)(smu + QT_OFF + c * 4096 + swz(row, c4 * 4)) = w;
        }
#pragma unroll
    for (int c = 0; c < 2; c++)
#pragma unroll
        for (int i = 0; i < 2; i++) {
            int row = r0 + 32 * i;
            const float* src = k + kgb + (size_t)row * KVDIM + c * 64 + c4 * 8;
            float4 v0 = *(const float4*)(src);
            float4 v1 = *(const float4*)(src + 4);
            uint4 w;
            w.x = pkh(v0.x, v0.y);
            w.y = pkh(v0.z, v0.w);
            w.z = pkh(v1.x, v1.y);
            w.w = pkh(v1.z, v1.w);
            *(uint4*)(smu + KT_OFF + c * 2048 + swz(row, c4 * 4)) = w;
        }
#pragma unroll
    for (int u = 0; u < 4; u++) {
        int idx = u * 256 + tid;
        int p = idx >> 5, d4 = idx & 31;
        const float* vb = v + kgb + (size_t)(2 * p) * KVDIM + d4 * 4;
        float4 v0 = *(const float4*)(vb);
        float4 v1 = *(const float4*)(vb + KVDIM);
        uint4 w;
        w.x = pkh(v0.x, v1.x);
        w.y = pkh(v0.y, v1.y);
        w.z = pkh(v0.z, v1.z);
        w.w = pkh(v0.w, v1.w);
        *(uint4*)(smu + VF_OFF + p * 136 + d4 * 4) = w;
    }
    __syncthreads();

    // ---- hoist Q fragments to registers (loop-invariant) ----
    uint32_t qf[2][4][4];
#pragma unroll
    for (int c = 0; c < 2; c++) {
        const uint32_t* Qb = smu + QT_OFF + c * 4096;
#pragma unroll
        for (int s = 0; s < 4; s++) {
            const uint32_t kw = s * 8 + lw;
            const uint32_t rr = wid * 16 + lr;
            qf[c][s][0] = Qb[swz(rr, kw)];
            qf[c][s][1] = Qb[swz(rr + 8, kw)];
            qf[c][s][2] = Qb[swz(rr, kw + 4)];
            qf[c][s][3] = Qb[swz(rr + 8, kw + 4)];
        }
    }

    float accO[16][4];
#pragma unroll
    for (int nt = 0; nt < 16; nt++)
#pragma unroll
        for (int e = 0; e < 4; e++) accO[nt][e] = 0.0f;
    float m_s[2] = {-INFINITY, -INFINITY};
    float l_s[2] = {0.0f, 0.0f};

    for (int ti = 0; ti < 32; ti++) {
        const int s0 = ti * 64;
        __syncthreads();   // K/V tiles ready

        // ---- S = QK^T (single-pass fp16) ----
        float accS[8][4];
#pragma unroll
        for (int nt = 0; nt < 8; nt++)
#pragma unroll
            for (int e = 0; e < 4; e++) accS[nt][e] = 0.0f;
#pragma unroll
        for (int c = 0; c < 2; c++) {
            const uint32_t* Kb = smu + KT_OFF + c * 2048;
#pragma unroll
            for (int s = 0; s < 4; s++) {
                const uint32_t kw = s * 8 + lw;
#pragma unroll
                for (int nt = 0; nt < 8; nt++) {
                    uint32_t n = nt * 8 + lr;
                    uint32_t b0 = Kb[swz(n, kw)], b1 = Kb[swz(n, kw + 4)];
                    mma16816h(accS[nt], qf[c][s][0], qf[c][s][1],
                              qf[c][s][2], qf[c][s][3], b0, b1);
                }
            }
        }

        // ---- mask + warp-local online softmax; P -> fp16 registers ----
        uint32_t ph[4][4];
        {
            const int ta = t0 + wid * 16 + lr;
            const int tb = ta + 8;
            float mx0 = -INFINITY, mx1 = -INFINITY;
#pragma unroll
            for (int nt = 0; nt < 8; nt++) {
                const int sc = s0 + nt * 8 + 2 * lw;
                if (sc     <= ta) accS[nt][0] += 1.0f;
                if (sc + 1 <= ta) accS[nt][1] += 1.0f;
                if (sc     <= tb) accS[nt][2] += 1.0f;
                if (sc + 1 <= tb) accS[nt][3] += 1.0f;
                mx0 = fmaxf(mx0, fmaxf(accS[nt][0], accS[nt][1]));
                mx1 = fmaxf(mx1, fmaxf(accS[nt][2], accS[nt][3]));
            }
            mx0 = fmaxf(mx0, __shfl_xor_sync(0xffffffffu, mx0, 1));
            mx0 = fmaxf(mx0, __shfl_xor_sync(0xffffffffu, mx0, 2));
            mx1 = fmaxf(mx1, __shfl_xor_sync(0xffffffffu, mx1, 1));
            mx1 = fmaxf(mx1, __shfl_xor_sync(0xffffffffu, mx1, 2));
            float mn0 = fmaxf(m_s[0], mx0);
            float mn1 = fmaxf(m_s[1], mx1);
            float fac0 = fexp(m_s[0] - mn0);
            float fac1 = fexp(m_s[1] - mn1);
            m_s[0] = mn0; m_s[1] = mn1;
#pragma unroll
            for (int nt = 0; nt < 16; nt++) {
                accO[nt][0] *= fac0; accO[nt][1] *= fac0;
                accO[nt][2] *= fac1; accO[nt][3] *= fac1;
            }
            float sum0 = 0.0f, sum1 = 0.0f;
#pragma unroll
            for (int nt = 0; nt < 8; nt++) {
                float p0 = fexp(accS[nt][0] - mn0);
                float p1 = fexp(accS[nt][1] - mn0);
                float p2 = fexp(accS[nt][2] - mn1);
                float p3 = fexp(accS[nt][3] - mn1);
                sum0 += p0 + p1;
                sum1 += p2 + p3;
                int kt = nt >> 1, e0 = (nt & 1) * 2;
                ph[kt][e0]     = pkh(p0, p1);
                ph[kt][e0 + 1] = pkh(p2, p3);
            }
            sum0 += __shfl_xor_sync(0xffffffffu, sum0, 1);
            sum0 += __shfl_xor_sync(0xffffffffu, sum0, 2);
            sum1 += __shfl_xor_sync(0xffffffffu, sum1, 1);
            sum1 += __shfl_xor_sync(0xffffffffu, sum1, 2);
            l_s[0] = l_s[0] * fac0 + sum0;
            l_s[1] = l_s[1] * fac1 + sum1;
        }

        // ---- prefetch next K/V ----
        float4 kr[8], vr0[4], vr1[4];
        const bool more = (ti + 1 < 32);
        if (more) {
            const int s0n = s0 + 64;
#pragma unroll
            for (int c = 0; c < 2; c++)
#pragma unroll
                for (int i = 0; i < 2; i++) {
                    const float* src = k + kgb +
                        (size_t)(s0n + r0 + 32 * i) * KVDIM + c * 64 + c4 * 8;
                    kr[(c * 2 + i) * 2]     = *(const float4*)(src);
                    kr[(c * 2 + i) * 2 + 1] = *(const float4*)(src + 4);
                }
#pragma unroll
            for (int u = 0; u < 4; u++) {
                int idx = u * 256 + tid;
                int p = idx >> 5, d4 = idx & 31;
                const float* vb = v + kgb + (size_t)(s0n + 2 * p) * KVDIM + d4 * 4;
                vr0[u] = *(const float4*)(vb);
                vr1[u] = *(const float4*)(vb + KVDIM);
            }
        }

        // ---- O += P @ V (fp16 single-pass) ----
#pragma unroll
        for (int ks = 0; ks < 4; ks++) {
            const uint32_t prow0 = (ks * 8 + lw) * 136;
            const uint32_t prow1 = (ks * 8 + lw + 4) * 136;
#pragma unroll
            for (int nt = 0; nt < 16; nt++) {
                uint32_t dcol = nt * 8 + lr;
                uint32_t v0w = smu[VF_OFF + prow0 + dcol];
                uint32_t v1w = smu[VF_OFF + prow1 + dcol];
                mma16816h(accO[nt], ph[ks][0], ph[ks][1], ph[ks][2], ph[ks][3],
                          v0w, v1w);
            }
        }

        __syncthreads();   // done reading K/V before overwrite

        if (more) {
#pragma unroll
            for (int c = 0; c < 2; c++)
#pragma unroll
                for (int i = 0; i < 2; i++) {
                    int row = r0 + 32 * i;
                    float4 v0 = kr[(c * 2 + i) * 2];
                    float4 v1 = kr[(c * 2 + i) * 2 + 1];
                    uint4 w;
                    w.x = pkh(v0.x, v0.y);
                    w.y = pkh(v0.z, v0.w);
                    w.z = pkh(v1.x, v1.y);
                    w.w = pkh(v1.z, v1.w);
                    *(uint4*)(smu + KT_OFF + c * 2048 + swz(row, c4 * 4)) = w;
                }
#pragma unroll
            for (int u = 0; u < 4; u++) {
                int idx = u * 256 + tid;
                int p = idx >> 5, d4 = idx & 31;
                uint4 w;
                w.x = pkh(vr0[u].x, vr1[u].x);
                w.y = pkh(vr0[u].y, vr1[u].y);
                w.z = pkh(vr0[u].z, vr1[u].z);
                w.w = pkh(vr0[u].w, vr1[u].w);
                *(uint4*)(smu + VF_OFF + p * 136 + d4 * 4) = w;
            }
        }
    }

    // ---- epilogue ----
    {
        float inv0 = 1.0f / l_s[0];
        float inv1 = 1.0f / l_s[1];
        int row = t0 + wid * 16 + lr;
#pragma unroll
        for (int nt = 0; nt < 16; nt++) {
            int col = h * 128 + nt * 8 + 2 * lw;
            *(float2*)(o + (size_t)(b * 2048 + row) * CDIM + col) =
                make_float2(accO[nt][0] * inv0, accO[nt][1] * inv0);
            *(float2*)(o + (size_t)(b * 2048 + row + 8) * CDIM + col) =
                make_float2(accO[nt][2] * inv1, accO[nt][3] * inv1);
        }
    }
}

extern "C" void kernel_launch(void* const* d_in, const int* in_sizes, int n_in,
                              void* d_out, int out_size)
{
    const float* x  = (const float*)d_in[0];
    const float* wq = (const float*)d_in[1];
    const float* bq = (const float*)d_in[2];
    const float* wk = (const float*)d_in[3];
    const float* bk = (const float*)d_in[4];
    const float* wv = (const float*)d_in[5];
    const float* bv = (const float*)d_in[6];
    const float* wo = (const float*)d_in[7];
    const float* bo = (const float*)d_in[8];
    float* out = (float*)d_out;

    float *qp, *kp, *vp, *ap;
    cudaGetSymbolAddress((void**)&qp, g_q);
    cudaGetSymbolAddress((void**)&kp, g_k);
    cudaGetSymbolAddress((void**)&vp, g_v);
    cudaGetSymbolAddress((void**)&ap, g_att);

    cudaFuncSetAttribute(gemm_mma,
                         cudaFuncAttributeMaxDynamicSharedMemorySize, GEMM_SMEM);
    cudaFuncSetAttribute(attn_mma,
                         cudaFuncAttributeMaxDynamicSharedMemorySize, ATT_SMEM_BYTES);

    gemm_mma<<<dim3(16, 32), 256, GEMM_SMEM>>>(x, wq, bq, qp, BT, CDIM, CDIM);
    gemm_mma<<<dim3(4, 32), 256, GEMM_SMEM>>>(x, wk, bk, kp, BT, KVDIM, CDIM);
    gemm_mma<<<dim3(4, 32), 256, GEMM_SMEM>>>(x, wv, bv, vp, BT, KVDIM, CDIM);

    rope_kernel<<<(BT * 16 * 64 + 255) / 256, 256>>>(qp, 16);
    rope_kernel<<<(BT * 4 * 64 + 255) / 256, 256>>>(kp, 4);

    attn_mma<<<dim3(16, 32), 256, ATT_SMEM_BYTES>>>(qp, kp, vp, ap);

    gemm_mma<<<dim3(16, 32), 256, GEMM_SMEM>>>(ap, wo, bo, out, BT, CDIM, CDIM);
}

// round 14
// speedup vs baseline: 3.6053x; 1.6823x over previous
#include <cuda_runtime.h>
#include <cuda_bf16.h>
#include <cuda_fp16.h>
#include <math.h>
#include <cstdint>
#include <cstring>

#define BT 4096
#define CDIM 2048
#define KVDIM 512

__device__ float g_q[(size_t)BT * CDIM];
__device__ float g_k[(size_t)BT * KVDIM];
__device__ float g_v[(size_t)BT * KVDIM];
__device__ float g_att[(size_t)BT * CDIM];

// fp16 mma
__device__ __forceinline__ void mma16816h(
    float c[4], uint32_t a0, uint32_t a1, uint32_t a2, uint32_t a3,
    uint32_t b0, uint32_t b1)
{
    asm volatile(
        "mma.sync.aligned.m16n8k16.row.col.f32.f16.f16.f32 "
        "{%0,%1,%2,%3}, {%4,%5,%6,%7}, {%8,%9}, {%0,%1,%2,%3};"
        : "+f"(c[0]), "+f"(c[1]), "+f"(c[2]), "+f"(c[3])
        : "r"(a0), "r"(a1), "r"(a2), "r"(a3), "r"(b0), "r"(b1));
}

// pack two floats into one fp16x2 word (a in low half)
__device__ __forceinline__ uint32_t pkh(float a, float b) {
    __half2 h = __floats2half2_rn(a, b);
    uint32_t r;
    memcpy(&r, &h, 4);
    return r;
}

// pack 8 floats (two float4) into uint4 of fp16x2
__device__ __forceinline__ uint4 pk8(float4 v0, float4 v1) {
    uint4 w;
    w.x = pkh(v0.x, v0.y);
    w.y = pkh(v0.z, v0.w);
    w.z = pkh(v1.x, v1.y);
    w.w = pkh(v1.z, v1.w);
    return w;
}

__device__ __forceinline__ uint32_t swz(uint32_t r, uint32_t w) {
    return r * 32u + (w ^ ((r & 7u) << 2));
}

// exp for x<=0 on FMA pipe
__device__ __forceinline__ float fexp(float x) {
    float t = fmaxf(x * 1.4426950408889634f, -126.0f);
    float r = rintf(t);
    float u = (t - r) * 0.6931471805599453f;
    float p = 0.008333333333f;
    p = fmaf(p, u, 0.041666666667f);
    p = fmaf(p, u, 0.166666666667f);
    p = fmaf(p, u, 0.5f);
    p = fmaf(p, u, 1.0f);
    p = fmaf(p, u, 1.0f);
    return p * __int_as_float(((int)r + 127) << 23);
}

// ===== fp16 single-pass NT GEMM: C = A[M,K] B[N,K]^T + bias =====
// CTA 128x128, 8 warps (2x4), chunk = 64 floats (128B fp16 row), 4 k16-steps.
// Double-buffered: 2 stages x (A 16KB + B 16KB) = 64KB.
#define GEMM_SMEM (4 * 16384)

__global__ __launch_bounds__(256) void gemm_mma_h(
    const float* __restrict__ A, const float* __restrict__ B,
    const float* __restrict__ bias, float* __restrict__ C,
    int M, int N, int K)
{
    extern __shared__ uint32_t smw[];
    const int tid = threadIdx.x;
    const int wid = tid >> 5, lane = tid & 31;
    const int bm = blockIdx.y * 128, bn = blockIdx.x * 128;
    const int wm = wid >> 2, wn = wid & 3;
    const int r0 = tid >> 3, c4 = tid & 7;   // 32 rows x 8 col-groups
    const float* Ag = A + (size_t)(bm + r0) * K + c4 * 8;
    const float* Bg = B + (size_t)(bn + r0) * K + c4 * 8;
    const size_t strA = (size_t)32 * K;
    const int nchunk = K >> 6;               // 32 for K=2048

    float acc[4][4][4];
#pragma unroll
    for (int mt = 0; mt < 4; mt++)
#pragma unroll
        for (int nt = 0; nt < 4; nt++)
#pragma unroll
            for (int e = 0; e < 4; e++) acc[mt][nt][e] = 0.0f;

    float4 ra[8], rb[8];   // 4 rows x 2 float4 per matrix
#pragma unroll
    for (int i = 0; i < 4; i++) {
        ra[i * 2]     = *(const float4*)(Ag + i * strA);
        ra[i * 2 + 1] = *(const float4*)(Ag + i * strA + 4);
        rb[i * 2]     = *(const float4*)(Bg + i * strA);
        rb[i * 2 + 1] = *(const float4*)(Bg + i * strA + 4);
    }
    {
        uint32_t* As = smw; uint32_t* Bs = smw + 4096;
#pragma unroll
        for (int i = 0; i < 4; i++) {
            uint32_t r = r0 + i * 32;
            *(uint4*)(As + swz(r, c4 * 4)) = pk8(ra[i * 2], ra[i * 2 + 1]);
            *(uint4*)(Bs + swz(r, c4 * 4)) = pk8(rb[i * 2], rb[i * 2 + 1]);
        }
    }
    const int lr = lane >> 2, lw = lane & 3;

    for (int c = 0; c < nchunk; ++c) {
        if (c + 1 < nchunk) {
#pragma unroll
            for (int i = 0; i < 4; i++) {
                ra[i * 2]     = *(const float4*)(Ag + (c + 1) * 64 + i * strA);
                ra[i * 2 + 1] = *(const float4*)(Ag + (c + 1) * 64 + i * strA + 4);
                rb[i * 2]     = *(const float4*)(Bg + (c + 1) * 64 + i * strA);
                rb[i * 2 + 1] = *(const float4*)(Bg + (c + 1) * 64 + i * strA + 4);
            }
        }
        __syncthreads();
        uint32_t* As = smw + (c & 1) * 8192;
        uint32_t* Bs = As + 4096;
#pragma unroll
        for (int s = 0; s < 4; s++) {
            const uint32_t kw = s * 8 + lw;
            uint32_t bfr[4][2];
#pragma unroll
            for (int nt = 0; nt < 4; nt++) {
                uint32_t n = wn * 32 + nt * 8 + lr;
                bfr[nt][0] = Bs[swz(n, kw)];
                bfr[nt][1] = Bs[swz(n, kw + 4)];
            }
#pragma unroll
            for (int mt = 0; mt < 4; mt++) {
                uint32_t rr = wm * 64 + mt * 16 + lr;
                uint32_t a0 = As[swz(rr, kw)], a1 = As[swz(rr + 8, kw)];
                uint32_t a2 = As[swz(rr, kw + 4)], a3 = As[swz(rr + 8, kw + 4)];
#pragma unroll
                for (int nt = 0; nt < 4; nt++)
                    mma16816h(acc[mt][nt], a0, a1, a2, a3, bfr[nt][0], bfr[nt][1]);
            }
        }
        if (c + 1 < nchunk) {
            uint32_t* An = smw + ((c + 1) & 1) * 8192;
            uint32_t* Bn = An + 4096;
#pragma unroll
            for (int i = 0; i < 4; i++) {
                uint32_t r = r0 + i * 32;
                *(uint4*)(An + swz(r, c4 * 4)) = pk8(ra[i * 2], ra[i * 2 + 1]);
                *(uint4*)(Bn + swz(r, c4 * 4)) = pk8(rb[i * 2], rb[i * 2 + 1]);
            }
        }
    }
#pragma unroll
    for (int mt = 0; mt < 4; mt++) {
        int row = bm + wm * 64 + mt * 16 + lr;
#pragma unroll
        for (int nt = 0; nt < 4; nt++) {
            int col = bn + wn * 32 + nt * 8 + lw * 2;
            float b0 = bias[col], b1 = bias[col + 1];
            *(float2*)(C + (size_t)row * N + col) =
                make_float2(acc[mt][nt][0] + b0, acc[mt][nt][1] + b1);
            *(float2*)(C + (size_t)(row + 8) * N + col) =
                make_float2(acc[mt][nt][2] + b0, acc[mt][nt][3] + b1);
        }
    }
}

__global__ void rope_kernel(float* __restrict__ data, int heads)
{
    int idx = blockIdx.x * blockDim.x + threadIdx.x;
    int total = BT * heads * 64;
    if (idx >= total) return;
    int d = idx & 63;
    int h = (idx >> 6) % heads;
    int row = idx / (heads * 64);
    float invf = powf(10000.0f, -(float)d / 64.0f);
    float ang = (float)h * invf;
    float c = cosf(ang), s = sinf(ang);
    float* p = data + (size_t)row * heads * 128 + h * 128;
    float x1 = p[d], x2 = p[d + 64];
    p[d] = x1 * c - x2 * s;
    p[d + 64] = x2 * c + x1 * s;
}

// ===== fp16 single-pass flash attention (unchanged from passing R13) =====
#define QT_OFF 0
#define KT_OFF 8192
#define VF_OFF 12288
#define ATT_SMEM_BYTES (16640 * 4)

__global__ __launch_bounds__(256, 1) void attn_mma(
    const float* __restrict__ q, const float* __restrict__ k,
    const float* __restrict__ v, float* __restrict__ o)
{
    extern __shared__ uint32_t smu[];

    const int tid = threadIdx.x;
    const int wid = tid >> 5, lane = tid & 31;
    const int lr = lane >> 2, lw = lane & 3;
    const int b = blockIdx.y >> 4, h = blockIdx.y & 15;
    const int kv = h >> 2;
    const int t0 = blockIdx.x * 128;
    const float scale = 0.08838834764831845f;
    const int r0 = tid >> 3, c4 = tid & 7;

    const size_t qgb = ((size_t)(b * 2048 + t0)) * CDIM + h * 128;
    const size_t kgb = ((size_t)(b * 2048)) * KVDIM + kv * 128;

#pragma unroll
    for (int c = 0; c < 2; c++)
#pragma unroll
        for (int i = 0; i < 4; i++) {
            int row = r0 + 32 * i;
            const float* src = q + qgb + (size_t)row * CDIM + c * 64 + c4 * 8;
            float4 v0 = *(const float4*)(src);
            float4 v1 = *(const float4*)(src + 4);
            uint4 w;
            w.x = pkh(v0.x * scale, v0.y * scale);
            w.y = pkh(v0.z * scale, v0.w * scale);
            w.z = pkh(v1.x * scale, v1.y * scale);
            w.w = pkh(v1.z * scale, v1.w * scale);
            *(uint4*)(smu + QT_OFF + c * 4096 + swz(row, c4 * 4)) = w;
        }
#pragma unroll
    for (int c = 0; c < 2; c++)
#pragma unroll
        for (int i = 0; i < 2; i++) {
            int row = r0 + 32 * i;
            const float* src = k + kgb + (size_t)row * KVDIM + c * 64 + c4 * 8;
            float4 v0 = *(const float4*)(src);
            float4 v1 = *(const float4*)(src + 4);
            *(uint4*)(smu + KT_OFF + c * 2048 + swz(row, c4 * 4)) = pk8(v0, v1);
        }
#pragma unroll
    for (int u = 0; u < 4; u++) {
        int idx = u * 256 + tid;
        int p = idx >> 5, d4 = idx & 31;
        const float* vb = v + kgb + (size_t)(2 * p) * KVDIM + d4 * 4;
        float4 v0 = *(const float4*)(vb);
        float4 v1 = *(const float4*)(vb + KVDIM);
        uint4 w;
        w.x = pkh(v0.x, v1.x);
        w.y = pkh(v0.y, v1.y);
        w.z = pkh(v0.z, v1.z);
        w.w = pkh(v0.w, v1.w);
        *(uint4*)(smu + VF_OFF + p * 136 + d4 * 4) = w;
    }
    __syncthreads();

    uint32_t qf[2][4][4];
#pragma unroll
    for (int c = 0; c < 2; c++) {
        const uint32_t* Qb = smu + QT_OFF + c * 4096;
#pragma unroll
        for (int s = 0; s < 4; s++) {
            const uint32_t kw = s * 8 + lw;
            const uint32_t rr = wid * 16 + lr;
            qf[c][s][0] = Qb[swz(rr, kw)];
            qf[c][s][1] = Qb[swz(rr + 8, kw)];
            qf[c][s][2] = Qb[swz(rr, kw + 4)];
            qf[c][s][3] = Qb[swz(rr + 8, kw + 4)];
        }
    }

    float accO[16][4];
#pragma unroll
    for (int nt = 0; nt < 16; nt++)
#pragma unroll
        for (int e = 0; e < 4; e++) accO[nt][e] = 0.0f;
    float m_s[2] = {-INFINITY, -INFINITY};
    float l_s[2] = {0.0f, 0.0f};

    for (int ti = 0; ti < 32; ti++) {
        const int s0 = ti * 64;
        __syncthreads();

        float accS[8][4];
#pragma unroll
        for (int nt = 0; nt < 8; nt++)
#pragma unroll
            for (int e = 0; e < 4; e++) accS[nt][e] = 0.0f;
#pragma unroll
        for (int c = 0; c < 2; c++) {
            const uint32_t* Kb = smu + KT_OFF + c * 2048;
#pragma unroll
            for (int s = 0; s < 4; s++) {
                const uint32_t kw = s * 8 + lw;
#pragma unroll
                for (int nt = 0; nt < 8; nt++) {
                    uint32_t n = nt * 8 + lr;
                    uint32_t b0 = Kb[swz(n, kw)], b1 = Kb[swz(n, kw + 4)];
                    mma16816h(accS[nt], qf[c][s][0], qf[c][s][1],
                              qf[c][s][2], qf[c][s][3], b0, b1);
                }
            }
        }

        uint32_t ph[4][4];
        {
            const int ta = t0 + wid * 16 + lr;
            const int tb = ta + 8;
            float mx0 = -INFINITY, mx1 = -INFINITY;
#pragma unroll
            for (int nt = 0; nt < 8; nt++) {
                const int sc = s0 + nt * 8 + 2 * lw;
                if (sc     <= ta) accS[nt][0] += 1.0f;
                if (sc + 1 <= ta) accS[nt][1] += 1.0f;
                if (sc     <= tb) accS[nt][2] += 1.0f;
                if (sc + 1 <= tb) accS[nt][3] += 1.0f;
                mx0 = fmaxf(mx0, fmaxf(accS[nt][0], accS[nt][1]));
                mx1 = fmaxf(mx1, fmaxf(accS[nt][2], accS[nt][3]));
            }
            mx0 = fmaxf(mx0, __shfl_xor_sync(0xffffffffu, mx0, 1));
            mx0 = fmaxf(mx0, __shfl_xor_sync(0xffffffffu, mx0, 2));
            mx1 = fmaxf(mx1, __shfl_xor_sync(0xffffffffu, mx1, 1));
            mx1 = fmaxf(mx1, __shfl_xor_sync(0xffffffffu, mx1, 2));
            float mn0 = fmaxf(m_s[0], mx0);
            float mn1 = fmaxf(m_s[1], mx1);
            float fac0 = fexp(m_s[0] - mn0);
            float fac1 = fexp(m_s[1] - mn1);
            m_s[0] = mn0; m_s[1] = mn1;
#pragma unroll
            for (int nt = 0; nt < 16; nt++) {
                accO[nt][0] *= fac0; accO[nt][1] *= fac0;
                accO[nt][2] *= fac1; accO[nt][3] *= fac1;
            }
            float sum0 = 0.0f, sum1 = 0.0f;
#pragma unroll
            for (int nt = 0; nt < 8; nt++) {
                float p0 = fexp(accS[nt][0] - mn0);
                float p1 = fexp(accS[nt][1] - mn0);
                float p2 = fexp(accS[nt][2] - mn1);
                float p3 = fexp(accS[nt][3] - mn1);
                sum0 += p0 + p1;
                sum1 += p2 + p3;
                int kt = nt >> 1, e0 = (nt & 1) * 2;
                ph[kt][e0]     = pkh(p0, p1);
                ph[kt][e0 + 1] = pkh(p2, p3);
            }
            sum0 += __shfl_xor_sync(0xffffffffu, sum0, 1);
            sum0 += __shfl_xor_sync(0xffffffffu, sum0, 2);
            sum1 += __shfl_xor_sync(0xffffffffu, sum1, 1);
            sum1 += __shfl_xor_sync(0xffffffffu, sum1, 2);
            l_s[0] = l_s[0] * fac0 + sum0;
            l_s[1] = l_s[1] * fac1 + sum1;
        }

        float4 kr[8], vr0[4], vr1[4];
        const bool more = (ti + 1 < 32);
        if (more) {
            const int s0n = s0 + 64;
#pragma unroll
            for (int c = 0; c < 2; c++)
#pragma unroll
                for (int i = 0; i < 2; i++) {
                    const float* src = k + kgb +
                        (size_t)(s0n + r0 + 32 * i) * KVDIM + c * 64 + c4 * 8;
                    kr[(c * 2 + i) * 2]     = *(const float4*)(src);
                    kr[(c * 2 + i) * 2 + 1] = *(const float4*)(src + 4);
                }
#pragma unroll
            for (int u = 0; u < 4; u++) {
                int idx = u * 256 + tid;
                int p = idx >> 5, d4 = idx & 31;
                const float* vb = v + kgb + (size_t)(s0n + 2 * p) * KVDIM + d4 * 4;
                vr0[u] = *(const float4*)(vb);
                vr1[u] = *(const float4*)(vb + KVDIM);
            }
        }

#pragma unroll
        for (int ks = 0; ks < 4; ks++) {
            const uint32_t prow0 = (ks * 8 + lw) * 136;
            const uint32_t prow1 = (ks * 8 + lw + 4) * 136;
#pragma unroll
            for (int nt = 0; nt < 16; nt++) {
                uint32_t dcol = nt * 8 + lr;
                uint32_t v0w = smu[VF_OFF + prow0 + dcol];
                uint32_t v1w = smu[VF_OFF + prow1 + dcol];
                mma16816h(accO[nt], ph[ks][0], ph[ks][1], ph[ks][2], ph[ks][3],
                          v0w, v1w);
            }
        }

        __syncthreads();

        if (more) {
#pragma unroll
            for (int c = 0; c < 2; c++)
#pragma unroll
                for (int i = 0; i < 2; i++) {
                    int row = r0 + 32 * i;
                    *(uint4*)(smu + KT_OFF + c * 2048 + swz(row, c4 * 4)) =
                        pk8(kr[(c * 2 + i) * 2], kr[(c * 2 + i) * 2 + 1]);
                }
#pragma unroll
            for (int u = 0; u < 4; u++) {
                int idx = u * 256 + tid;
                int p = idx >> 5, d4 = idx & 31;
                uint4 w;
                w.x = pkh(vr0[u].x, vr1[u].x);
                w.y = pkh(vr0[u].y, vr1[u].y);
                w.z = pkh(vr0[u].z, vr1[u].z);
                w.w = pkh(vr0[u].w, vr1[u].w);
                *(uint4*)(smu + VF_OFF + p * 136 + d4 * 4) = w;
            }
        }
    }

    {
        float inv0 = 1.0f / l_s[0];
        float inv1 = 1.0f / l_s[1];
        int row = t0 + wid * 16 + lr;
#pragma unroll
        for (int nt = 0; nt < 16; nt++) {
            int col = h * 128 + nt * 8 + 2 * lw;
            *(float2*)(o + (size_t)(b * 2048 + row) * CDIM + col) =
                make_float2(accO[nt][0] * inv0, accO[nt][1] * inv0);
            *(float2*)(o + (size_t)(b * 2048 + row + 8) * CDIM + col) =
                make_float2(accO[nt][2] * inv1, accO[nt][3] * inv1);
        }
    }
}

extern "C" void kernel_launch(void* const* d_in, const int* in_sizes, int n_in,
                              void* d_out, int out_size)
{
    const float* x  = (const float*)d_in[0];
    const float* wq = (const float*)d_in[1];
    const float* bq = (const float*)d_in[2];
    const float* wk = (const float*)d_in[3];
    const float* bk = (const float*)d_in[4];
    const float* wv = (const float*)d_in[5];
    const float* bv = (const float*)d_in[6];
    const float* wo = (const float*)d_in[7];
    const float* bo = (const float*)d_in[8];
    float* out = (float*)d_out;

    float *qp, *kp, *vp, *ap;
    cudaGetSymbolAddress((void**)&qp, g_q);
    cudaGetSymbolAddress((void**)&kp, g_k);
    cudaGetSymbolAddress((void**)&vp, g_v);
    cudaGetSymbolAddress((void**)&ap, g_att);

    cudaFuncSetAttribute(gemm_mma_h,
                         cudaFuncAttributeMaxDynamicSharedMemorySize, GEMM_SMEM);
    cudaFuncSetAttribute(attn_mma,
                         cudaFuncAttributeMaxDynamicSharedMemorySize, ATT_SMEM_BYTES);

    gemm_mma_h<<<dim3(16, 32), 256, GEMM_SMEM>>>(x, wq, bq, qp, BT, CDIM, CDIM);
    gemm_mma_h<<<dim3(4, 32), 256, GEMM_SMEM>>>(x, wk, bk, kp, BT, KVDIM, CDIM);
    gemm_mma_h<<<dim3(4, 32), 256, GEMM_SMEM>>>(x, wv, bv, vp, BT, KVDIM, CDIM);

    rope_kernel<<<(BT * 16 * 64 + 255) / 256, 256>>>(qp, 16);
    rope_kernel<<<(BT * 4 * 64 + 255) / 256, 256>>>(kp, 4);

    attn_mma<<<dim3(16, 32), 256, ATT_SMEM_BYTES>>>(qp, kp, vp, ap);

    gemm_mma_h<<<dim3(16, 32), 256, GEMM_SMEM>>>(ap, wo, bo, out, BT, CDIM, CDIM);
}

// round 16
// speedup vs baseline: 4.0423x; 1.1212x over previous
#include <cuda_runtime.h>
#include <cuda_fp16.h>
#include <math.h>
#include <cstdint>
#include <cstring>

#define BT 4096
#define CDIM 2048
#define KVDIM 512

// fp16 scratch (word = fp16x2)
__device__ __align__(16) uint32_t g_qh[(size_t)BT * 1024];   // [row][h*64+w]
__device__ __align__(16) uint32_t g_kh[(size_t)BT * 256];    // [row][kv*64+w]
__device__ __align__(16) uint32_t g_vh[(size_t)8 * 1024 * 128]; // [(b*4+kv)*1024+p][d]
__device__ float g_att[(size_t)BT * CDIM];

__device__ __forceinline__ void mma16816h(
    float c[4], uint32_t a0, uint32_t a1, uint32_t a2, uint32_t a3,
    uint32_t b0, uint32_t b1)
{
    asm volatile(
        "mma.sync.aligned.m16n8k16.row.col.f32.f16.f16.f32 "
        "{%0,%1,%2,%3}, {%4,%5,%6,%7}, {%8,%9}, {%0,%1,%2,%3};"
        : "+f"(c[0]), "+f"(c[1]), "+f"(c[2]), "+f"(c[3])
        : "r"(a0), "r"(a1), "r"(a2), "r"(a3), "r"(b0), "r"(b1));
}

__device__ __forceinline__ uint32_t pkh(float a, float b) {
    __half2 h = __floats2half2_rn(a, b);
    uint32_t r;
    memcpy(&r, &h, 4);
    return r;
}

__device__ __forceinline__ uint4 pk8(float4 v0, float4 v1) {
    uint4 w;
    w.x = pkh(v0.x, v0.y);
    w.y = pkh(v0.z, v0.w);
    w.z = pkh(v1.x, v1.y);
    w.w = pkh(v1.z, v1.w);
    return w;
}

__device__ __forceinline__ uint32_t swz(uint32_t r, uint32_t w) {
    return r * 32u + (w ^ ((r & 7u) << 2));
}

// exp for x<=0 on FMA pipe
__device__ __forceinline__ float fexp(float x) {
    float t = fmaxf(x * 1.4426950408889634f, -126.0f);
    float r = rintf(t);
    float u = (t - r) * 0.6931471805599453f;
    float p = 0.008333333333f;
    p = fmaf(p, u, 0.041666666667f);
    p = fmaf(p, u, 0.166666666667f);
    p = fmaf(p, u, 0.5f);
    p = fmaf(p, u, 1.0f);
    p = fmaf(p, u, 1.0f);
    return p * __int_as_float(((int)r + 127) << 23);
}

// ===========================================================================
// fp16 single-pass NT GEMM with fused epilogue.
// MODE 0: fp32 out (wo).  MODE 1: rope+scale -> fp16 q.  MODE 2: rope -> fp16 k.
// MODE 3: k-paired fp16 v.
// CTA 128x128, 8 warps (2x4), chunk = 64 floats, double-buffered.
// ===========================================================================
#define GEMM_SMEM 66048   // max(2*32KB stages, 128x129 fp32 staging)

template <int MODE>
__global__ __launch_bounds__(256) void gemm_mma_h(
    const float* __restrict__ A, const float* __restrict__ B,
    const float* __restrict__ bias, float* __restrict__ Cf,
    uint32_t* __restrict__ Ch, int M, int N, int K)
{
    extern __shared__ uint32_t smw[];
    const int tid = threadIdx.x;
    const int wid = tid >> 5, lane = tid & 31;
    const int bm = blockIdx.y * 128, bn = blockIdx.x * 128;
    const int wm = wid >> 2, wn = wid & 3;
    const int r0 = tid >> 3, c4 = tid & 7;
    const float* Ag = A + (size_t)(bm + r0) * K + c4 * 8;
    const float* Bg = B + (size_t)(bn + r0) * K + c4 * 8;
    const size_t strA = (size_t)32 * K;
    const int nchunk = K >> 6;

    float acc[4][4][4];
#pragma unroll
    for (int mt = 0; mt < 4; mt++)
#pragma unroll
        for (int nt = 0; nt < 4; nt++)
#pragma unroll
            for (int e = 0; e < 4; e++) acc[mt][nt][e] = 0.0f;

    float4 ra[8], rb[8];
#pragma unroll
    for (int i = 0; i < 4; i++) {
        ra[i * 2]     = *(const float4*)(Ag + i * strA);
        ra[i * 2 + 1] = *(const float4*)(Ag + i * strA + 4);
        rb[i * 2]     = *(const float4*)(Bg + i * strA);
        rb[i * 2 + 1] = *(const float4*)(Bg + i * strA + 4);
    }
    {
        uint32_t* As = smw; uint32_t* Bs = smw + 4096;
#pragma unroll
        for (int i = 0; i < 4; i++) {
            uint32_t r = r0 + i * 32;
            *(uint4*)(As + swz(r, c4 * 4)) = pk8(ra[i * 2], ra[i * 2 + 1]);
            *(uint4*)(Bs + swz(r, c4 * 4)) = pk8(rb[i * 2], rb[i * 2 + 1]);
        }
    }
    const int lr = lane >> 2, lw = lane & 3;

    for (int c = 0; c < nchunk; ++c) {
        if (c + 1 < nchunk) {
#pragma unroll
            for (int i = 0; i < 4; i++) {
                ra[i * 2]     = *(const float4*)(Ag + (c + 1) * 64 + i * strA);
                ra[i * 2 + 1] = *(const float4*)(Ag + (c + 1) * 64 + i * strA + 4);
                rb[i * 2]     = *(const float4*)(Bg + (c + 1) * 64 + i * strA);
                rb[i * 2 + 1] = *(const float4*)(Bg + (c + 1) * 64 + i * strA + 4);
            }
        }
        __syncthreads();
        uint32_t* As = smw + (c & 1) * 8192;
        uint32_t* Bs = As + 4096;
#pragma unroll
        for (int s = 0; s < 4; s++) {
            const uint32_t kw = s * 8 + lw;
            uint32_t bfr[4][2];
#pragma unroll
            for (int nt = 0; nt < 4; nt++) {
                uint32_t n = wn * 32 + nt * 8 + lr;
                bfr[nt][0] = Bs[swz(n, kw)];
                bfr[nt][1] = Bs[swz(n, kw + 4)];
            }
#pragma unroll
            for (int mt = 0; mt < 4; mt++) {
                uint32_t rr = wm * 64 + mt * 16 + lr;
                uint32_t a0 = As[swz(rr, kw)], a1 = As[swz(rr + 8, kw)];
                uint32_t a2 = As[swz(rr, kw + 4)], a3 = As[swz(rr + 8, kw + 4)];
#pragma unroll
                for (int nt = 0; nt < 4; nt++)
                    mma16816h(acc[mt][nt], a0, a1, a2, a3, bfr[nt][0], bfr[nt][1]);
            }
        }
        if (c + 1 < nchunk) {
            uint32_t* An = smw + ((c + 1) & 1) * 8192;
            uint32_t* Bn = An + 4096;
#pragma unroll
            for (int i = 0; i < 4; i++) {
                uint32_t r = r0 + i * 32;
                *(uint4*)(An + swz(r, c4 * 4)) = pk8(ra[i * 2], ra[i * 2 + 1]);
                *(uint4*)(Bn + swz(r, c4 * 4)) = pk8(rb[i * 2], rb[i * 2 + 1]);
            }
        }
    }

    if (MODE == 0) {
#pragma unroll
        for (int mt = 0; mt < 4; mt++) {
            int row = bm + wm * 64 + mt * 16 + lr;
#pragma unroll
            for (int nt = 0; nt < 4; nt++) {
                int col = bn + wn * 32 + nt * 8 + lw * 2;
                float b0 = bias[col], b1 = bias[col + 1];
                *(float2*)(Cf + (size_t)row * N + col) =
                    make_float2(acc[mt][nt][0] + b0, acc[mt][nt][1] + b1);
                *(float2*)(Cf + (size_t)(row + 8) * N + col) =
                    make_float2(acc[mt][nt][2] + b0, acc[mt][nt][3] + b1);
            }
        }
        return;
    }

    // staged epilogue: acc+bias -> smem [128][129] fp32
    __syncthreads();
    float* ep = (float*)smw;
#pragma unroll
    for (int mt = 0; mt < 4; mt++) {
        int rl = wm * 64 + mt * 16 + lr;
#pragma unroll
        for (int nt = 0; nt < 4; nt++) {
            int col = wn * 32 + nt * 8 + lw * 2;
            float b0 = bias[bn + col], b1 = bias[bn + col + 1];
            ep[rl * 129 + col]           = acc[mt][nt][0] + b0;
            ep[rl * 129 + col + 1]       = acc[mt][nt][1] + b1;
            ep[(rl + 8) * 129 + col]     = acc[mt][nt][2] + b0;
            ep[(rl + 8) * 129 + col + 1] = acc[mt][nt][3] + b1;
        }
    }
    __syncthreads();

    const int hh = bn >> 7;   // head index within its tensor
    if (MODE == 1 || MODE == 2) {
        const int OSTR = (MODE == 1) ? 1024 : 256;
        const float qs = (MODE == 1) ? 0.08838834764831845f : 1.0f;
        const float hf = (float)hh;
#pragma unroll 4
        for (int j = 0; j < 32; j++) {
            int w = tid + j * 256;       // 8192 words
            int tl = w >> 6, wd = w & 63;
            int d0 = wd * 2, d1 = d0 + 1;
            float v0 = ep[tl * 129 + d0];
            float v1 = ep[tl * 129 + d1];
            float p0 = ep[tl * 129 + (d0 ^ 64)];
            float p1 = ep[tl * 129 + (d1 ^ 64)];
            float i0 = __powf(10000.0f, -(float)(d0 & 63) * 0.015625f);
            float i1 = __powf(10000.0f, -(float)(d1 & 63) * 0.015625f);
            float s0, c0, s1, c1;
            __sincosf(hf * i0, &s0, &c0);
            __sincosf(hf * i1, &s1, &c1);
            float r0v = (d0 < 64) ? -p0 : p0;
            float r1v = (d1 < 64) ? -p1 : p1;
            float o0 = (v0 * c0 + r0v * s0) * qs;
            float o1 = (v1 * c1 + r1v * s1) * qs;
            Ch[(size_t)(bm + tl) * OSTR + hh * 64 + wd] = pkh(o0, o1);
        }
    } else {  // MODE 3: V pairing
        const size_t b4 = (size_t)(bm >> 11) * 4 + hh;
        const int tp0 = (bm & 2047) >> 1;
#pragma unroll 4
        for (int j = 0; j < 32; j++) {
            int w = tid + j * 256;       // 8192 words
            int p = w >> 7, d = w & 127;
            float v0 = ep[(2 * p) * 129 + d];
            float v1 = ep[(2 * p + 1) * 129 + d];
            Ch[(b4 * 1024 + tp0 + p) * 128 + d] = pkh(v0, v1);
        }
    }
}

// ===========================================================================
// fp16 flash attention: raw-copy loads (scale+rope already applied)
// ===========================================================================
#define QT_OFF 0
#define KT_OFF 8192
#define VF_OFF 12288
#define ATT_SMEM_BYTES (16640 * 4)

__global__ __launch_bounds__(256, 1) void attn_mma(
    const uint32_t* __restrict__ qh, const uint32_t* __restrict__ kh,
    const uint32_t* __restrict__ vh, float* __restrict__ o)
{
    extern __shared__ uint32_t smu[];

    const int tid = threadIdx.x;
    const int wid = tid >> 5, lane = tid & 31;
    const int lr = lane >> 2, lw = lane & 3;
    const int b = blockIdx.y >> 4, h = blockIdx.y & 15;
    const int kv = h >> 2;
    const int t0 = blockIdx.x * 128;
    const int r0 = tid >> 3, c4 = tid & 7;

    const size_t qgb = (size_t)(b * 2048 + t0) * 1024 + h * 64;
    const size_t kgb = (size_t)(b * 2048) * 256 + kv * 64;
    const size_t vgb = (size_t)(b * 4 + kv) * 1024 * 128;

    // prologue: raw copies
#pragma unroll
    for (int c = 0; c < 2; c++)
#pragma unroll
        for (int i = 0; i < 4; i++) {
            int row = r0 + 32 * i;
            *(uint4*)(smu + QT_OFF + c * 4096 + swz(row, c4 * 4)) =
                *(const uint4*)(qh + qgb + (size_t)row * 1024 + c * 32 + c4 * 4);
        }
#pragma unroll
    for (int c = 0; c < 2; c++)
#pragma unroll
        for (int i = 0; i < 2; i++) {
            int row = r0 + 32 * i;
            *(uint4*)(smu + KT_OFF + c * 2048 + swz(row, c4 * 4)) =
                *(const uint4*)(kh + kgb + (size_t)row * 256 + c * 32 + c4 * 4);
        }
#pragma unroll
    for (int u = 0; u < 4; u++) {
        int idx = u * 256 + tid;
        int p = idx >> 5, d4 = idx & 31;
        *(uint4*)(smu + VF_OFF + p * 136 + d4 * 4) =
            *(const uint4*)(vh + vgb + (size_t)p * 128 + d4 * 4);
    }
    __syncthreads();

    uint32_t qf[2][4][4];
#pragma unroll
    for (int c = 0; c < 2; c++) {
        const uint32_t* Qb = smu + QT_OFF + c * 4096;
#pragma unroll
        for (int s = 0; s < 4; s++) {
            const uint32_t kw = s * 8 + lw;
            const uint32_t rr = wid * 16 + lr;
            qf[c][s][0] = Qb[swz(rr, kw)];
            qf[c][s][1] = Qb[swz(rr + 8, kw)];
            qf[c][s][2] = Qb[swz(rr, kw + 4)];
            qf[c][s][3] = Qb[swz(rr + 8, kw + 4)];
        }
    }

    float accO[16][4];
#pragma unroll
    for (int nt = 0; nt < 16; nt++)
#pragma unroll
        for (int e = 0; e < 4; e++) accO[nt][e] = 0.0f;
    float m_s[2] = {-INFINITY, -INFINITY};
    float l_s[2] = {0.0f, 0.0f};

    for (int ti = 0; ti < 32; ti++) {
        const int s0 = ti * 64;
        __syncthreads();

        float accS[8][4];
#pragma unroll
        for (int nt = 0; nt < 8; nt++)
#pragma unroll
            for (int e = 0; e < 4; e++) accS[nt][e] = 0.0f;
#pragma unroll
        for (int c = 0; c < 2; c++) {
            const uint32_t* Kb = smu + KT_OFF + c * 2048;
#pragma unroll
            for (int s = 0; s < 4; s++) {
                const uint32_t kw = s * 8 + lw;
#pragma unroll
                for (int nt = 0; nt < 8; nt++) {
                    uint32_t n = nt * 8 + lr;
                    uint32_t b0 = Kb[swz(n, kw)], b1 = Kb[swz(n, kw + 4)];
                    mma16816h(accS[nt], qf[c][s][0], qf[c][s][1],
                              qf[c][s][2], qf[c][s][3], b0, b1);
                }
            }
        }

        uint32_t ph[4][4];
        {
            const int ta = t0 + wid * 16 + lr;
            const int tb = ta + 8;
            float mx0 = -INFINITY, mx1 = -INFINITY;
#pragma unroll
            for (int nt = 0; nt < 8; nt++) {
                const int sc = s0 + nt * 8 + 2 * lw;
                if (sc     <= ta) accS[nt][0] += 1.0f;
                if (sc + 1 <= ta) accS[nt][1] += 1.0f;
                if (sc     <= tb) accS[nt][2] += 1.0f;
                if (sc + 1 <= tb) accS[nt][3] += 1.0f;
                mx0 = fmaxf(mx0, fmaxf(accS[nt][0], accS[nt][1]));
                mx1 = fmaxf(mx1, fmaxf(accS[nt][2], accS[nt][3]));
            }
            mx0 = fmaxf(mx0, __shfl_xor_sync(0xffffffffu, mx0, 1));
            mx0 = fmaxf(mx0, __shfl_xor_sync(0xffffffffu, mx0, 2));
            mx1 = fmaxf(mx1, __shfl_xor_sync(0xffffffffu, mx1, 1));
            mx1 = fmaxf(mx1, __shfl_xor_sync(0xffffffffu, mx1, 2));
            float mn0 = fmaxf(m_s[0], mx0);
            float mn1 = fmaxf(m_s[1], mx1);
            float fac0 = fexp(m_s[0] - mn0);
            float fac1 = fexp(m_s[1] - mn1);
            m_s[0] = mn0; m_s[1] = mn1;
#pragma unroll
            for (int nt = 0; nt < 16; nt++) {
                accO[nt][0] *= fac0; accO[nt][1] *= fac0;
                accO[nt][2] *= fac1; accO[nt][3] *= fac1;
            }
            float sum0 = 0.0f, sum1 = 0.0f;
#pragma unroll
            for (int nt = 0; nt < 8; nt++) {
                float p0 = fexp(accS[nt][0] - mn0);
                float p1 = fexp(accS[nt][1] - mn0);
                float p2 = fexp(accS[nt][2] - mn1);
                float p3 = fexp(accS[nt][3] - mn1);
                sum0 += p0 + p1;
                sum1 += p2 + p3;
                int kt = nt >> 1, e0 = (nt & 1) * 2;
                ph[kt][e0]     = pkh(p0, p1);
                ph[kt][e0 + 1] = pkh(p2, p3);
            }
            sum0 += __shfl_xor_sync(0xffffffffu, sum0, 1);
            sum0 += __shfl_xor_sync(0xffffffffu, sum0, 2);
            sum1 += __shfl_xor_sync(0xffffffffu, sum1, 1);
            sum1 += __shfl_xor_sync(0xffffffffu, sum1, 2);
            l_s[0] = l_s[0] * fac0 + sum0;
            l_s[1] = l_s[1] * fac1 + sum1;
        }

        uint4 kr[4], vr[4];
        const bool more = (ti + 1 < 32);
        if (more) {
            const int s0n = s0 + 64;
#pragma unroll
            for (int c = 0; c < 2; c++)
#pragma unroll
                for (int i = 0; i < 2; i++)
                    kr[c * 2 + i] = *(const uint4*)(kh + kgb +
                        (size_t)(s0n + r0 + 32 * i) * 256 + c * 32 + c4 * 4);
#pragma unroll
            for (int u = 0; u < 4; u++) {
                int idx = u * 256 + tid;
                int p = idx >> 5, d4 = idx & 31;
                vr[u] = *(const uint4*)(vh + vgb +
                    (size_t)(s0n / 2 + p) * 128 + d4 * 4);
            }
        }

#pragma unroll
        for (int ks = 0; ks < 4; ks++) {
            const uint32_t prow0 = (ks * 8 + lw) * 136;
            const uint32_t prow1 = (ks * 8 + lw + 4) * 136;
#pragma unroll
            for (int nt = 0; nt < 16; nt++) {
                uint32_t dcol = nt * 8 + lr;
                uint32_t v0w = smu[VF_OFF + prow0 + dcol];
                uint32_t v1w = smu[VF_OFF + prow1 + dcol];
                mma16816h(accO[nt], ph[ks][0], ph[ks][1], ph[ks][2], ph[ks][3],
                          v0w, v1w);
            }
        }

        __syncthreads();

        if (more) {
#pragma unroll
            for (int c = 0; c < 2; c++)
#pragma unroll
                for (int i = 0; i < 2; i++) {
                    int row = r0 + 32 * i;
                    *(uint4*)(smu + KT_OFF + c * 2048 + swz(row, c4 * 4)) =
                        kr[c * 2 + i];
                }
#pragma unroll
            for (int u = 0; u < 4; u++) {
                int idx = u * 256 + tid;
                int p = idx >> 5, d4 = idx & 31;
                *(uint4*)(smu + VF_OFF + p * 136 + d4 * 4) = vr[u];
            }
        }
    }

    {
        float inv0 = 1.0f / l_s[0];
        float inv1 = 1.0f / l_s[1];
        int row = t0 + wid * 16 + lr;
#pragma unroll
        for (int nt = 0; nt < 16; nt++) {
            int col = h * 128 + nt * 8 + 2 * lw;
            *(float2*)(o + (size_t)(b * 2048 + row) * CDIM + col) =
                make_float2(accO[nt][0] * inv0, accO[nt][1] * inv0);
            *(float2*)(o + (size_t)(b * 2048 + row + 8) * CDIM + col) =
                make_float2(accO[nt][2] * inv1, accO[nt][3] * inv1);
        }
    }
}

extern "C" void kernel_launch(void* const* d_in, const int* in_sizes, int n_in,
                              void* d_out, int out_size)
{
    const float* x  = (const float*)d_in[0];
    const float* wq = (const float*)d_in[1];
    const float* bq = (const float*)d_in[2];
    const float* wk = (const float*)d_in[3];
    const float* bk = (const float*)d_in[4];
    const float* wv = (const float*)d_in[5];
    const float* bv = (const float*)d_in[6];
    const float* wo = (const float*)d_in[7];
    const float* bo = (const float*)d_in[8];
    float* out = (float*)d_out;

    uint32_t *qp, *kp, *vp;
    float *ap;
    cudaGetSymbolAddress((void**)&qp, g_qh);
    cudaGetSymbolAddress((void**)&kp, g_kh);
    cudaGetSymbolAddress((void**)&vp, g_vh);
    cudaGetSymbolAddress((void**)&ap, g_att);

    cudaFuncSetAttribute(gemm_mma_h<0>,
                         cudaFuncAttributeMaxDynamicSharedMemorySize, GEMM_SMEM);
    cudaFuncSetAttribute(gemm_mma_h<1>,
                         cudaFuncAttributeMaxDynamicSharedMemorySize, GEMM_SMEM);
    cudaFuncSetAttribute(gemm_mma_h<2>,
                         cudaFuncAttributeMaxDynamicSharedMemorySize, GEMM_SMEM);
    cudaFuncSetAttribute(gemm_mma_h<3>,
                         cudaFuncAttributeMaxDynamicSharedMemorySize, GEMM_SMEM);
    cudaFuncSetAttribute(attn_mma,
                         cudaFuncAttributeMaxDynamicSharedMemorySize, ATT_SMEM_BYTES);

    gemm_mma_h<1><<<dim3(16, 32), 256, GEMM_SMEM>>>(x, wq, bq, nullptr, qp, BT, CDIM, CDIM);
    gemm_mma_h<2><<<dim3(4, 32), 256, GEMM_SMEM>>>(x, wk, bk, nullptr, kp, BT, KVDIM, CDIM);
    gemm_mma_h<3><<<dim3(4, 32), 256, GEMM_SMEM>>>(x, wv, bv, nullptr, vp, BT, KVDIM, CDIM);

    attn_mma<<<dim3(16, 32), 256, ATT_SMEM_BYTES>>>(qp, kp, vp, ap);

    gemm_mma_h<0><<<dim3(16, 32), 256, GEMM_SMEM>>>(ap, wo, bo, out, nullptr, BT, CDIM, CDIM);
}